// round 7
// baseline (speedup 1.0000x reference)
#include <cuda_runtime.h>
#include <cuda_bf16.h>
#include <math.h>
#include <stdint.h>

// ---------------------------------------------------------------------------
// Problem constants (fixed shapes)
// ---------------------------------------------------------------------------
#define Bb     2
#define Ll     2048
#define Dm     1024
#define Hh     32
#define Pp     64
#define Nn     128
#define KCONV  4
#define Ck     256
#define Nc     8          // Ll / Ck
#define Inter  2048
#define ConvD  2304
#define ProjD  4384
#define BL     (Bb * Ll)  // 4096

// ---------------------------------------------------------------------------
// Scratch (device globals; no dynamic allocation allowed)
// ---------------------------------------------------------------------------
__device__ float g_proj[(size_t)BL * ProjD];
__device__ float g_conv[(size_t)BL * ConvD];
__device__ float g_dtv[(size_t)BL * Hh];
__device__ float g_acum[(size_t)Bb * Nc * Hh * Ck];
__device__ float g_gm[(size_t)Bb * Nc * Ck * Ck];
__device__ float g_y[(size_t)BL * Inter];
__device__ float g_states[(size_t)Bb * Nc * Hh * Pp * Nn];
__device__ float g_prev[(size_t)Bb * Nc * Hh * Pp * Nn];

// bf16 split buffers
__device__ __nv_bfloat16 g_Ah[(size_t)BL * Inter];
__device__ __nv_bfloat16 g_Al[(size_t)BL * Inter];
__device__ __nv_bfloat16 g_Bh[(size_t)ProjD * Dm];
__device__ __nv_bfloat16 g_Bl[(size_t)ProjD * Dm];

__device__ __forceinline__ float siluf(float x) { return x / (1.f + expf(-x)); }

// ---------------------------------------------------------------------------
// PTX helpers
// ---------------------------------------------------------------------------
__device__ __forceinline__ unsigned su32(const void* p) {
    return (unsigned)__cvta_generic_to_shared(p);
}

__device__ __forceinline__ void cp16(unsigned dst, const void* src, bool ok) {
    int sz = ok ? 16 : 0;
    asm volatile("cp.async.cg.shared.global [%0], [%1], 16, %2;\n"
                 :: "r"(dst), "l"(src), "r"(sz));
}

__device__ __forceinline__ void ldsm4(unsigned& r0, unsigned& r1, unsigned& r2, unsigned& r3,
                                      unsigned addr) {
    asm volatile("ldmatrix.sync.aligned.m8n8.x4.shared.b16 {%0,%1,%2,%3}, [%4];"
                 : "=r"(r0), "=r"(r1), "=r"(r2), "=r"(r3) : "r"(addr));
}

__device__ __forceinline__ void mma16816(float* c, const unsigned* a, const unsigned* b) {
    asm volatile(
        "mma.sync.aligned.m16n8k16.row.col.f32.bf16.bf16.f32 "
        "{%0,%1,%2,%3}, {%4,%5,%6,%7}, {%8,%9}, {%0,%1,%2,%3};"
        : "+f"(c[0]), "+f"(c[1]), "+f"(c[2]), "+f"(c[3])
        : "r"(a[0]), "r"(a[1]), "r"(a[2]), "r"(a[3]), "r"(b[0]), "r"(b[1]));
}

// ---------------------------------------------------------------------------
// Tensor-core bf16-split GEMM (unchanged from R6)
// ---------------------------------------------------------------------------
#define GEMM_SMEM (2 * 73728)

struct Frags {
    unsigned ah[4][4], al[4][4];
    unsigned bh[4][2], bl[4][2];
};

__device__ __forceinline__ void load_frags(Frags& F, unsigned stg, int ks,
                                           int wm, int wn, int lane) {
    const int rA = lane & 15;
    const int cB = ((lane >> 4) << 4);
    const unsigned colb = (unsigned)(ks * 32 + cB);
#pragma unroll
    for (int mf = 0; mf < 4; mf++) {
        unsigned ra = stg + (wm * 64 + mf * 16 + rA) * 144 + colb;
        ldsm4(F.ah[mf][0], F.ah[mf][1], F.ah[mf][2], F.ah[mf][3], ra);
        ldsm4(F.al[mf][0], F.al[mf][1], F.al[mf][2], F.al[mf][3], ra + 18432);
    }
#pragma unroll
    for (int nf2 = 0; nf2 < 2; nf2++) {
        unsigned rb = stg + 36864 + (wn * 32 + nf2 * 16 + rA) * 144 + colb;
        unsigned t0, t1, t2, t3;
        ldsm4(t0, t1, t2, t3, rb);
        F.bh[nf2 * 2][0] = t0; F.bh[nf2 * 2][1] = t2;
        F.bh[nf2 * 2 + 1][0] = t1; F.bh[nf2 * 2 + 1][1] = t3;
        ldsm4(t0, t1, t2, t3, rb + 18432);
        F.bl[nf2 * 2][0] = t0; F.bl[nf2 * 2][1] = t2;
        F.bl[nf2 * 2 + 1][0] = t1; F.bl[nf2 * 2 + 1][1] = t3;
    }
}

__device__ __forceinline__ void gemm_core(const __nv_bfloat16* __restrict__ Ah,
                                          const __nv_bfloat16* __restrict__ Al,
                                          const __nv_bfloat16* __restrict__ Bh,
                                          const __nv_bfloat16* __restrict__ Bl,
                                          float* __restrict__ C,
                                          int M, int N, int K) {
    extern __shared__ char dyn[];
    const unsigned sbase = su32(dyn);
    const int tid = threadIdx.x;
    const int lane = tid & 31;
    const int warp = tid >> 5;
    const int wm = warp >> 2;
    const int wn = warp & 3;
    const int m0 = blockIdx.y * 128;
    const int n0 = blockIdx.x * 128;
    const int KB = K >> 6;

    float acc[4][4][4];
#pragma unroll
    for (int a = 0; a < 4; a++)
#pragma unroll
        for (int b = 0; b < 4; b++)
#pragma unroll
            for (int c = 0; c < 4; c++) acc[a][b][c] = 0.f;

    auto issue = [&](int kc, int st) {
        unsigned stg = sbase + st * 73728;
#pragma unroll
        for (int i = 0; i < 16; i++) {
            int q = tid + (i << 8);
            int mat = q >> 10;
            int r = (q >> 3) & 127;
            int c16 = q & 7;
            const __nv_bfloat16* base = (mat == 0) ? Ah : (mat == 1) ? Al : (mat == 2) ? Bh : Bl;
            int gr = ((mat < 2) ? m0 : n0) + r;
            bool ok = gr < ((mat < 2) ? M : N);
            if (!ok) gr = ((mat < 2) ? M : N) - 1;
            const void* src = base + (size_t)gr * K + (kc << 6) + (c16 << 3);
            unsigned dst = stg + mat * 18432 + r * 144 + (c16 << 4);
            cp16(dst, src, ok);
        }
        asm volatile("cp.async.commit_group;\n");
    };

    issue(0, 0);
    if (KB > 1) issue(1, 1);

    Frags F[2];

    for (int kb = 0; kb < KB; kb++) {
        int st = kb & 1;
        if (kb + 1 < KB) asm volatile("cp.async.wait_group 1;\n");
        else             asm volatile("cp.async.wait_group 0;\n");
        __syncthreads();
        unsigned stg = sbase + st * 73728;

        load_frags(F[0], stg, 0, wm, wn, lane);
#pragma unroll
        for (int ks = 0; ks < 4; ks++) {
            if (ks < 3) load_frags(F[(ks + 1) & 1], stg, ks + 1, wm, wn, lane);
            Frags& f = F[ks & 1];
#pragma unroll
            for (int mf = 0; mf < 4; mf++)
#pragma unroll
                for (int nf = 0; nf < 4; nf++) {
                    mma16816(acc[mf][nf], f.ah[mf], f.bh[nf]);
                    mma16816(acc[mf][nf], f.ah[mf], f.bl[nf]);
                    mma16816(acc[mf][nf], f.al[mf], f.bh[nf]);
                }
        }
        __syncthreads();
        if (kb + 2 < KB) issue(kb + 2, st);
    }

    int g4 = lane >> 2, t4 = lane & 3;
#pragma unroll
    for (int mf = 0; mf < 4; mf++) {
        int r0 = m0 + wm * 64 + mf * 16 + g4;
#pragma unroll
        for (int nf = 0; nf < 4; nf++) {
            int cg = n0 + wn * 32 + nf * 8 + t4 * 2;
            if (cg < N) {
                float* p0 = C + (size_t)r0 * N + cg;
                p0[0] = acc[mf][nf][0];
                p0[1] = acc[mf][nf][1];
                float* p1 = p0 + (size_t)8 * N;
                p1[0] = acc[mf][nf][2];
                p1[1] = acc[mf][nf][3];
            }
        }
    }
}

__global__ __launch_bounds__(256) void gemm_in_kernel() {
    gemm_core(g_Ah, g_Al, g_Bh, g_Bl, g_proj, BL, ProjD, Dm);
}

__global__ __launch_bounds__(256) void gemm_out_kernel(float* __restrict__ out) {
    gemm_core(g_Ah, g_Al, g_Bh, g_Bl, out, BL, Dm, Inter);
}

// ---------------------------------------------------------------------------
// bf16 split conversions
// ---------------------------------------------------------------------------
__global__ void split_x_kernel(const float* __restrict__ in, int n) {
    int i = blockIdx.x * blockDim.x + threadIdx.x;
    if (i >= n) return;
    float v = in[i];
    __nv_bfloat16 h = __float2bfloat16(v);
    g_Ah[i] = h;
    g_Al[i] = __float2bfloat16(v - __bfloat162float(h));
}

__global__ void split_w_kernel(const float* __restrict__ in, int n) {
    int i = blockIdx.x * blockDim.x + threadIdx.x;
    if (i >= n) return;
    float v = in[i];
    __nv_bfloat16 h = __float2bfloat16(v);
    g_Bh[i] = h;
    g_Bl[i] = __float2bfloat16(v - __bfloat162float(h));
}

// ---------------------------------------------------------------------------
// Depthwise causal conv1d + SiLU (sliding window, unchanged)
// ---------------------------------------------------------------------------
__global__ __launch_bounds__(256) void conv_silu_kernel(const float* __restrict__ cw,
                                                        const float* __restrict__ cb) {
    int ch = blockIdx.x * 256 + threadIdx.x;
    int l0 = blockIdx.y * 64;
    int b  = blockIdx.z;
    const float* col = g_proj + (size_t)b * Ll * ProjD + Inter + ch;
    float w0 = cw[ch * KCONV + 0];
    float w1 = cw[ch * KCONV + 1];
    float w2 = cw[ch * KCONV + 2];
    float w3 = cw[ch * KCONV + 3];
    float bias = cb[ch];
    float xm3 = (l0 >= 3) ? col[(size_t)(l0 - 3) * ProjD] : 0.f;
    float xm2 = (l0 >= 2) ? col[(size_t)(l0 - 2) * ProjD] : 0.f;
    float xm1 = (l0 >= 1) ? col[(size_t)(l0 - 1) * ProjD] : 0.f;
    float* outp = g_conv + (size_t)(b * Ll + l0) * ConvD + ch;
#pragma unroll 4
    for (int i = 0; i < 64; i++) {
        float x0 = col[(size_t)(l0 + i) * ProjD];
        float acc = bias + w0 * xm3 + w1 * xm2 + w2 * xm1 + w3 * x0;
        outp[(size_t)i * ConvD] = siluf(acc);
        xm3 = xm2; xm2 = xm1; xm1 = x0;
    }
}

// ---------------------------------------------------------------------------
// Per-chunk inclusive cumsum of dt * A with fused softplus
// ---------------------------------------------------------------------------
__global__ void acum_kernel(const float* __restrict__ A_log,
                            const float* __restrict__ dt_bias) {
    int blk = blockIdx.x;
    int h = blk % Hh;
    int bc = blk / Hh;
    int b = bc / Nc, c = bc % Nc;
    int t = threadIdx.x;
    float A = -expf(A_log[h]);
    int bl = b * Ll + c * Ck + t;
    float raw = g_proj[(size_t)bl * ProjD + Inter + ConvD + h] + dt_bias[h];
    float dt = (raw > 20.f) ? raw : log1pf(expf(raw));
    g_dtv[(size_t)bl * Hh + h] = dt;
    float v = dt * A;
    __shared__ float s[Ck];
    s[t] = v;
    __syncthreads();
    for (int off = 1; off < Ck; off <<= 1) {
        float x = (t >= off) ? s[t - off] : 0.f;
        __syncthreads();
        s[t] += x;
        __syncthreads();
    }
    g_acum[(size_t)blk * Ck + t] = s[t];
}

// ---------------------------------------------------------------------------
// Gm[s,z] = sum_n C[s,n] * B[z,n] per (b,c), lower triangle tiles (unchanged)
// ---------------------------------------------------------------------------
__global__ __launch_bounds__(256) void gm_kernel() {
    int bc = blockIdx.x;
    int sT = blockIdx.y, zT = blockIdx.z;
    if (zT > sT) return;
    int b = bc / Nc, c = bc % Nc;
    int rowbase = b * Ll + c * Ck;
    __shared__ float Cs[16][65];
    __shared__ float Bs[16][65];
    int tid = threadIdx.x;
    int ty = tid >> 4, tx = tid & 15;
    float acc[4][4];
#pragma unroll
    for (int i = 0; i < 4; i++)
#pragma unroll
        for (int j = 0; j < 4; j++) acc[i][j] = 0.f;

    int lrow = tid >> 2;
    int lcol = (tid & 3) * 4;

    for (int n0 = 0; n0 < Nn; n0 += 16) {
        const float* pc = g_conv + (size_t)(rowbase + sT * 64 + lrow) * ConvD + Inter + Nn + n0 + lcol;
        const float* pb = g_conv + (size_t)(rowbase + zT * 64 + lrow) * ConvD + Inter + n0 + lcol;
#pragma unroll
        for (int u = 0; u < 4; u++) Cs[lcol + u][lrow] = pc[u];
#pragma unroll
        for (int u = 0; u < 4; u++) Bs[lcol + u][lrow] = pb[u];
        __syncthreads();
#pragma unroll
        for (int kk = 0; kk < 16; kk++) {
            float rc[4], rb[4];
#pragma unroll
            for (int i = 0; i < 4; i++) rc[i] = Cs[kk][ty * 4 + i];
#pragma unroll
            for (int j = 0; j < 4; j++) rb[j] = Bs[kk][tx * 4 + j];
#pragma unroll
            for (int i = 0; i < 4; i++)
#pragma unroll
                for (int j = 0; j < 4; j++) acc[i][j] += rc[i] * rb[j];
        }
        __syncthreads();
    }
#pragma unroll
    for (int i = 0; i < 4; i++) {
        int sg = sT * 64 + ty * 4 + i;
        float* pg = g_gm + ((size_t)bc * Ck + sg) * Ck + zT * 64 + tx * 4;
#pragma unroll
        for (int j = 0; j < 4; j++) pg[j] = acc[i][j];
    }
}

// ---------------------------------------------------------------------------
// Y_diag — exp-factored, block=(bc,h), 256s x 64p, 8x8 micro, z-chunks of 32.
// exp(As - Az) = exp(As - M)*exp(M - Az) per chunk (M = chunk-end cumsum;
// both exponents <= 0). Only the diagonal 32x32 needs per-entry exp.
// ---------------------------------------------------------------------------
__global__ __launch_bounds__(256) void ydiag_kernel() {
    int bc = blockIdx.x;
    int h = blockIdx.y;
    int b = bc / Nc, c = bc % Nc;
    int tid = threadIdx.x;
    int ty = tid >> 3;       // 0..31 (s-group)
    int tx = tid & 7;        // 0..7  (p-group)
    int cs = ty >> 2;        // this thread's s-chunk (its 8 s are in one chunk)

    __shared__ float W[32][257];   // [z][s]
    __shared__ float Hs[32][65];   // [z][p] raw hs*dt
    __shared__ float sAc[256];
    __shared__ float ezs[32];

    const float* acumC = g_acum + ((size_t)bc * Hh + h) * Ck;
    sAc[tid] = acumC[tid];
    int rowbase = b * Ll + c * Ck;

    float acc[8][8];
#pragma unroll
    for (int i = 0; i < 8; i++)
#pragma unroll
        for (int j = 0; j < 8; j++) acc[i][j] = 0.f;

    __syncthreads();

    for (int zc = 0; zc < 8; zc++) {
        float M = sAc[zc * 32 + 31];
        // phase A: load Hs (raw) and ez
        {
            int zz = tid >> 3;
            int p0 = (tid & 7) * 8;
            int l = rowbase + zc * 32 + zz;
            float d = g_dtv[(size_t)l * Hh + h];
            const float* ph = g_conv + (size_t)l * ConvD + h * Pp + p0;
#pragma unroll
            for (int u = 0; u < 8; u++) Hs[zz][p0 + u] = ph[u] * d;
        }
        if (tid < 32) ezs[tid] = expf(M - sAc[zc * 32 + tid]);
        __syncthreads();
        // phase B: build W column s = tid
        {
            int s = tid;
            int scn = s >> 5;
            const float* grow = g_gm + ((size_t)bc * Ck + s) * Ck + zc * 32;
            if (scn > zc) {
                float es = expf(sAc[s] - M);
#pragma unroll 8
                for (int z = 0; z < 32; z++)
                    W[z][s] = grow[z] * ezs[z] * es;
            } else if (scn == zc) {
                int zmax = s & 31;
                float as = sAc[s];
                for (int z = 0; z < 32; z++)
                    W[z][s] = (z <= zmax) ? grow[z] * expf(as - sAc[zc * 32 + z]) : 0.f;
            }
        }
        __syncthreads();
        // phase C: FMA (warp-uniform causal skip: warp covers one s-chunk)
        if (cs >= zc) {
#pragma unroll 4
            for (int z = 0; z < 32; z++) {
                float rm[8], rh[8];
#pragma unroll
                for (int i = 0; i < 8; i++) rm[i] = W[z][ty * 8 + i];
#pragma unroll
                for (int j = 0; j < 8; j++) rh[j] = Hs[z][tx * 8 + j];
#pragma unroll
                for (int i = 0; i < 8; i++)
#pragma unroll
                    for (int j = 0; j < 8; j++) acc[i][j] += rm[i] * rh[j];
            }
        }
        __syncthreads();
    }
#pragma unroll
    for (int i = 0; i < 8; i++) {
        int l = rowbase + ty * 8 + i;
        float* py = g_y + (size_t)l * Inter + h * Pp + tx * 8;
#pragma unroll
        for (int j = 0; j < 8; j++) py[j] = acc[i][j];
    }
}

// ---------------------------------------------------------------------------
// states — block=(bc, h-pair): out [128 (2h x 64p)][128 n], 8x8 micro.
// B tile shared across the two heads.
// ---------------------------------------------------------------------------
__global__ __launch_bounds__(256) void states_kernel() {
    int bc = blockIdx.x;
    int hp = blockIdx.y;           // 0..15
    int h0 = hp * 2;
    int b = bc / Nc, c = bc % Nc;
    int tid = threadIdx.x;
    int ty = tid >> 4;             // 0..15 (row group: r = ty*8+i, r=[h_l*64+p])
    int tx = tid & 15;             // 0..15 (n group)
    int rowbase = b * Ll + c * Ck;

    __shared__ float Hd[32][129];  // [l][r]  (r = h_l*64 + p), scaled
    __shared__ float Bs[32][129];  // [l][n]
    __shared__ float ws[32][2];    // per-(l,h_l) weight for current chunk

    const float* acum0 = g_acum + ((size_t)bc * Hh + h0) * Ck;
    const float* acum1 = acum0 + Ck;
    float aL0 = acum0[Ck - 1];
    float aL1 = acum1[Ck - 1];

    float acc[8][8];
#pragma unroll
    for (int i = 0; i < 8; i++)
#pragma unroll
        for (int j = 0; j < 8; j++) acc[i][j] = 0.f;

    for (int lc = 0; lc < 8; lc++) {
        if (tid < 64) {
            int ll = tid >> 1, hl = tid & 1;
            int lg = lc * 32 + ll;
            float a = hl ? expf(aL1 - acum1[lg]) : expf(aL0 - acum0[lg]);
            ws[ll][hl] = g_dtv[(size_t)(rowbase + lg) * Hh + h0 + hl] * a;
        }
        __syncthreads();
        {
            int ll = tid >> 3;
            int r0 = (tid & 7) * 16;
            int l = rowbase + lc * 32 + ll;
            int hl = r0 >> 6;                 // constant over the 16 (r0 mult of 16)
            int p0 = r0 & 63;
            float w = ws[ll][hl];
            const float* ph = g_conv + (size_t)l * ConvD + (h0 + hl) * Pp + p0;
#pragma unroll
            for (int u = 0; u < 16; u++) Hd[ll][r0 + u] = ph[u] * w;
            int n0v = (tid & 7) * 16;
            const float* pb = g_conv + (size_t)l * ConvD + Inter + n0v;
#pragma unroll
            for (int u = 0; u < 16; u++) Bs[ll][n0v + u] = pb[u];
        }
        __syncthreads();
#pragma unroll 4
        for (int ll = 0; ll < 32; ll++) {
            float rh[8], rb[8];
#pragma unroll
            for (int i = 0; i < 8; i++) rh[i] = Hd[ll][ty * 8 + i];
#pragma unroll
            for (int j = 0; j < 8; j++) rb[j] = Bs[ll][tx * 8 + j];
#pragma unroll
            for (int i = 0; i < 8; i++)
#pragma unroll
                for (int j = 0; j < 8; j++) acc[i][j] += rh[i] * rb[j];
        }
        __syncthreads();
    }
#pragma unroll
    for (int i = 0; i < 8; i++) {
        int r = ty * 8 + i;
        int hl = r >> 6, p = r & 63;
        float* ps = g_states + (((size_t)bc * Hh + h0 + hl) * Pp + p) * Nn + tx * 8;
#pragma unroll
        for (int j = 0; j < 8; j++) ps[j] = acc[i][j];
    }
}

// ---------------------------------------------------------------------------
// Inter-chunk recurrence (unchanged)
// ---------------------------------------------------------------------------
__global__ void prev_kernel() {
    int idx = blockIdx.x * blockDim.x + threadIdx.x;
    if (idx >= Bb * Hh * Pp * Nn) return;
    int n = idx % Nn;
    int p = (idx / Nn) % Pp;
    int h = (idx / (Nn * Pp)) % Hh;
    int b = idx / (Nn * Pp * Hh);
    float r = 0.f;
    for (int c = 0; c < Nc; c++) {
        size_t off = (((size_t)(b * Nc + c) * Hh + h) * Pp + p) * Nn + n;
        g_prev[off] = r;
        float zl = g_acum[((size_t)(b * Nc + c) * Hh + h) * Ck + (Ck - 1)];
        r = g_states[off] + expf(zl) * r;
    }
}

// ---------------------------------------------------------------------------
// Y_off + combine — block=(bc,h): out [256 l][64 p], K=128 n, 8x8 micro.
// ---------------------------------------------------------------------------
__global__ __launch_bounds__(256) void yoff_kernel(const float* __restrict__ Dv) {
    int bc = blockIdx.x;
    int h = blockIdx.y;
    int b = bc / Nc, c = bc % Nc;
    int tid = threadIdx.x;
    int ty = tid >> 3;       // 0..31 (l-group)
    int tx = tid & 7;        // 0..7  (p-group)
    int rowbase = b * Ll + c * Ck;

    __shared__ float Cs[16][257];   // [n][l]
    __shared__ float Ps[16][65];    // [n][p]

    const float* acumC = g_acum + ((size_t)bc * Hh + h) * Ck;
    const float* pprev = g_prev + ((size_t)bc * Hh + h) * Pp * Nn;

    float acc[8][8];
#pragma unroll
    for (int i = 0; i < 8; i++)
#pragma unroll
        for (int j = 0; j < 8; j++) acc[i][j] = 0.f;

    for (int nc = 0; nc < 8; nc++) {
        {
            // C: thread t loads l=t, n = nc*16..+16 -> Cs[n][l]
            const float* pc = g_conv + (size_t)(rowbase + tid) * ConvD + Inter + Nn + nc * 16;
#pragma unroll
            for (int k = 0; k < 16; k++) Cs[k][tid] = pc[k];
            // prev: thread loads p = tid>>2, n = nc*16 + (tid&3)*4..+4
            int p = tid >> 2, k0 = (tid & 3) * 4;
            const float* pp = pprev + (size_t)p * Nn + nc * 16 + k0;
#pragma unroll
            for (int u = 0; u < 4; u++) Ps[k0 + u][p] = pp[u];
        }
        __syncthreads();
#pragma unroll 4
        for (int k = 0; k < 16; k++) {
            float rc[8], rp[8];
#pragma unroll
            for (int i = 0; i < 8; i++) rc[i] = Cs[k][ty * 8 + i];
#pragma unroll
            for (int j = 0; j < 8; j++) rp[j] = Ps[k][tx * 8 + j];
#pragma unroll
            for (int i = 0; i < 8; i++)
#pragma unroll
                for (int j = 0; j < 8; j++) acc[i][j] += rc[i] * rp[j];
        }
        __syncthreads();
    }
    float Dh = Dv[h];
#pragma unroll
    for (int i = 0; i < 8; i++) {
        int ls = ty * 8 + i;
        int l = rowbase + ls;
        float sd = expf(acumC[ls]);
        const float* ph = g_conv + (size_t)l * ConvD + h * Pp + tx * 8;
        float* py = g_y + (size_t)l * Inter + h * Pp + tx * 8;
#pragma unroll
        for (int j = 0; j < 8; j++)
            py[j] = py[j] + acc[i][j] * sd + Dh * ph[j];
    }
}

// ---------------------------------------------------------------------------
// Gated RMSNorm; writes bf16 hi/lo splits directly (unchanged)
// ---------------------------------------------------------------------------
__global__ __launch_bounds__(256) void norm_kernel(const float* __restrict__ norm_w) {
    int row = blockIdx.x;
    int tid = threadIdx.x;
    const float* pg = g_proj + (size_t)row * ProjD;
    const float* py = g_y + (size_t)row * Inter;
    float f[8];
    float ss = 0.f;
#pragma unroll
    for (int u = 0; u < 8; u++) {
        int i = tid + u * 256;
        float g = pg[i];
        float v = py[i] * siluf(g);
        f[u] = v;
        ss += v * v;
    }
    __shared__ float red[8];
    int lane = tid & 31, wid = tid >> 5;
#pragma unroll
    for (int o = 16; o > 0; o >>= 1) ss += __shfl_xor_sync(0xffffffffu, ss, o);
    if (lane == 0) red[wid] = ss;
    __syncthreads();
    if (tid == 0) {
        float t = 0.f;
#pragma unroll
        for (int i = 0; i < 8; i++) t += red[i];
        red[0] = t;
    }
    __syncthreads();
    float rs = rsqrtf(red[0] / (float)Inter + 1e-6f);
#pragma unroll
    for (int u = 0; u < 8; u++) {
        int i = tid + u * 256;
        float v = f[u] * rs * norm_w[i];
        __nv_bfloat16 h = __float2bfloat16(v);
        size_t o = (size_t)row * Inter + i;
        g_Ah[o] = h;
        g_Al[o] = __float2bfloat16(v - __bfloat162float(h));
    }
}

// ---------------------------------------------------------------------------
// Launch
// ---------------------------------------------------------------------------
extern "C" void kernel_launch(void* const* d_in, const int* in_sizes, int n_in,
                              void* d_out, int out_size) {
    const float* x         = (const float*)d_in[0];
    const float* in_proj_w = (const float*)d_in[1];
    const float* conv_w    = (const float*)d_in[2];
    const float* conv_b    = (const float*)d_in[3];
    const float* dt_bias   = (const float*)d_in[4];
    const float* A_log     = (const float*)d_in[5];
    const float* Dv        = (const float*)d_in[6];
    const float* norm_w    = (const float*)d_in[7];
    const float* out_proj_w= (const float*)d_in[8];
    float* out = (float*)d_out;

    cudaFuncSetAttribute(gemm_in_kernel, cudaFuncAttributeMaxDynamicSharedMemorySize, GEMM_SMEM);
    cudaFuncSetAttribute(gemm_out_kernel, cudaFuncAttributeMaxDynamicSharedMemorySize, GEMM_SMEM);

    // 1) split x and in_proj_w to bf16 hi/lo
    {
        int n = BL * Dm;
        split_x_kernel<<<(n + 255) / 256, 256>>>(x, n);
        n = ProjD * Dm;
        split_w_kernel<<<(n + 255) / 256, 256>>>(in_proj_w, n);
    }
    // 2) in-projection GEMM
    {
        dim3 grid((ProjD + 127) / 128, BL / 128);
        gemm_in_kernel<<<grid, 256, GEMM_SMEM>>>();
    }
    // 3) conv + SiLU
    {
        dim3 grid(ConvD / 256, Ll / 64, Bb);
        conv_silu_kernel<<<grid, 256>>>(conv_w, conv_b);
    }
    // 4) cumsum of dt*A (fused softplus)
    acum_kernel<<<Bb * Nc * Hh, Ck>>>(A_log, dt_bias);
    // 5) Gm = C B^T
    {
        dim3 grid(Bb * Nc, Ck / 64, Ck / 64);
        gm_kernel<<<grid, 256>>>();
    }
    // 6) Y_diag (exp-factored)
    {
        dim3 grid(Bb * Nc, Hh);
        ydiag_kernel<<<grid, 256>>>();
    }
    // 7) states (2 heads per block)
    {
        dim3 grid(Bb * Nc, Hh / 2);
        states_kernel<<<grid, 256>>>();
    }
    // 8) inter-chunk recurrence
    {
        int total = Bb * Hh * Pp * Nn;
        prev_kernel<<<(total + 255) / 256, 256>>>();
    }
    // 9) Y_off + combine
    {
        dim3 grid(Bb * Nc, Hh);
        yoff_kernel<<<grid, 256>>>(Dv);
    }
    // 10) gated RMSNorm (writes bf16 splits)
    norm_kernel<<<BL, 256>>>(norm_w);
    // 11) split out_proj_w
    {
        int n = Dm * Inter;
        split_w_kernel<<<(n + 255) / 256, 256>>>(out_proj_w, n);
    }
    // 12) out-projection GEMM
    {
        dim3 grid(Dm / 128, BL / 128);
        gemm_out_kernel<<<grid, 256, GEMM_SMEM>>>(out);
    }
    (void)in_sizes; (void)n_in; (void)out_size;
}

// round 8
// speedup vs baseline: 1.2542x; 1.2542x over previous
#include <cuda_runtime.h>
#include <cuda_fp16.h>
#include <math.h>
#include <stdint.h>

// ---------------------------------------------------------------------------
// Problem constants (fixed shapes)
// ---------------------------------------------------------------------------
#define Bb     2
#define Ll     2048
#define Dm     1024
#define Hh     32
#define Pp     64
#define Nn     128
#define KCONV  4
#define Ck     256
#define Nc     8          // Ll / Ck
#define Inter  2048
#define ConvD  2304
#define ProjD  4384
#define BL     (Bb * Ll)  // 4096

// ---------------------------------------------------------------------------
// Scratch (device globals; no dynamic allocation allowed)
// ---------------------------------------------------------------------------
__device__ float g_proj[(size_t)BL * ProjD];
__device__ float g_conv[(size_t)BL * ConvD];
__device__ float g_dtv[(size_t)BL * Hh];
__device__ float g_acum[(size_t)Bb * Nc * Hh * Ck];
__device__ float g_gm[(size_t)Bb * Nc * Ck * Ck];
__device__ float g_y[(size_t)BL * Inter];
__device__ float g_states[(size_t)Bb * Nc * Hh * Pp * Nn];
__device__ float g_prev[(size_t)Bb * Nc * Hh * Pp * Nn];

// fp16 split buffers: A = Ah + Al (exact to ~2^-22), B rounded to fp16
__device__ __half g_Ah[(size_t)BL * Inter];
__device__ __half g_Al[(size_t)BL * Inter];
__device__ __half g_Bh[(size_t)ProjD * Dm];

__device__ __forceinline__ float siluf(float x) { return x / (1.f + expf(-x)); }

// ---------------------------------------------------------------------------
// PTX helpers
// ---------------------------------------------------------------------------
__device__ __forceinline__ unsigned su32(const void* p) {
    return (unsigned)__cvta_generic_to_shared(p);
}

__device__ __forceinline__ void cp16(unsigned dst, const void* src, bool ok) {
    int sz = ok ? 16 : 0;
    asm volatile("cp.async.cg.shared.global [%0], [%1], 16, %2;\n"
                 :: "r"(dst), "l"(src), "r"(sz));
}

__device__ __forceinline__ void ldsm4(unsigned& r0, unsigned& r1, unsigned& r2, unsigned& r3,
                                      unsigned addr) {
    asm volatile("ldmatrix.sync.aligned.m8n8.x4.shared.b16 {%0,%1,%2,%3}, [%4];"
                 : "=r"(r0), "=r"(r1), "=r"(r2), "=r"(r3) : "r"(addr));
}

__device__ __forceinline__ void mma16816(float* c, const unsigned* a, const unsigned* b) {
    asm volatile(
        "mma.sync.aligned.m16n8k16.row.col.f32.f16.f16.f32 "
        "{%0,%1,%2,%3}, {%4,%5,%6,%7}, {%8,%9}, {%0,%1,%2,%3};"
        : "+f"(c[0]), "+f"(c[1]), "+f"(c[2]), "+f"(c[3])
        : "r"(a[0]), "r"(a[1]), "r"(a[2]), "r"(a[3]), "r"(b[0]), "r"(b[1]));
}

// ---------------------------------------------------------------------------
// Tensor-core fp16-split GEMM: C[M,N] = A[M,K] * B[N,K]^T
// 2-pass: C = Ah*Bh + Al*Bh  (== exact-A x fp16-rounded-B, fp32 accum)
// Tile 128x128x64, 256 threads (8 warps: 2(m) x 4(n)), warp tile 64x32.
// smem row = 64 fp16 = 128 B + 16 pad = 144 B. Stage = 3 mats x 128 x 144
// = 55296 B; 2 stages = 110592 B dynamic smem.
// ---------------------------------------------------------------------------
#define GEMM_SMEM (2 * 55296)

struct Frags {
    unsigned ah[4][4], al[4][4];
    unsigned bh[4][2];
};

__device__ __forceinline__ void load_frags(Frags& F, unsigned stg, int ks,
                                           int wm, int wn, int lane) {
    const int rA = lane & 15;
    const int cB = ((lane >> 4) << 4);
    const unsigned colb = (unsigned)(ks * 32 + cB);
#pragma unroll
    for (int mf = 0; mf < 4; mf++) {
        unsigned ra = stg + (wm * 64 + mf * 16 + rA) * 144 + colb;
        ldsm4(F.ah[mf][0], F.ah[mf][1], F.ah[mf][2], F.ah[mf][3], ra);
        ldsm4(F.al[mf][0], F.al[mf][1], F.al[mf][2], F.al[mf][3], ra + 18432);
    }
#pragma unroll
    for (int nf2 = 0; nf2 < 2; nf2++) {
        unsigned rb = stg + 36864 + (wn * 32 + nf2 * 16 + rA) * 144 + colb;
        unsigned t0, t1, t2, t3;
        ldsm4(t0, t1, t2, t3, rb);
        F.bh[nf2 * 2][0] = t0; F.bh[nf2 * 2][1] = t2;
        F.bh[nf2 * 2 + 1][0] = t1; F.bh[nf2 * 2 + 1][1] = t3;
    }
}

__device__ __forceinline__ void gemm_core(const __half* __restrict__ Ah,
                                          const __half* __restrict__ Al,
                                          const __half* __restrict__ Bh,
                                          float* __restrict__ C,
                                          int M, int N, int K) {
    extern __shared__ char dyn[];
    const unsigned sbase = su32(dyn);
    const int tid = threadIdx.x;
    const int lane = tid & 31;
    const int warp = tid >> 5;
    const int wm = warp >> 2;
    const int wn = warp & 3;
    const int m0 = blockIdx.y * 128;
    const int n0 = blockIdx.x * 128;
    const int KB = K >> 6;

    float acc[4][4][4];
#pragma unroll
    for (int a = 0; a < 4; a++)
#pragma unroll
        for (int b = 0; b < 4; b++)
#pragma unroll
            for (int c = 0; c < 4; c++) acc[a][b][c] = 0.f;

    auto issue = [&](int kc, int st) {
        unsigned stg = sbase + st * 55296;
#pragma unroll
        for (int i = 0; i < 12; i++) {
            int q = tid + (i << 8);           // 0..3071
            int mat = q >> 10;                // 0:Ah 1:Al 2:Bh
            int r = (q >> 3) & 127;
            int c16 = q & 7;
            const __half* base = (mat == 0) ? Ah : (mat == 1) ? Al : Bh;
            int gr = ((mat < 2) ? m0 : n0) + r;
            bool ok = gr < ((mat < 2) ? M : N);
            if (!ok) gr = ((mat < 2) ? M : N) - 1;
            const void* src = base + (size_t)gr * K + (kc << 6) + (c16 << 3);
            unsigned dst = stg + mat * 18432 + r * 144 + (c16 << 4);
            cp16(dst, src, ok);
        }
        asm volatile("cp.async.commit_group;\n");
    };

    issue(0, 0);
    if (KB > 1) issue(1, 1);

    Frags F[2];

    for (int kb = 0; kb < KB; kb++) {
        int st = kb & 1;
        if (kb + 1 < KB) asm volatile("cp.async.wait_group 1;\n");
        else             asm volatile("cp.async.wait_group 0;\n");
        __syncthreads();
        unsigned stg = sbase + st * 55296;

        load_frags(F[0], stg, 0, wm, wn, lane);
#pragma unroll
        for (int ks = 0; ks < 4; ks++) {
            if (ks < 3) load_frags(F[(ks + 1) & 1], stg, ks + 1, wm, wn, lane);
            Frags& f = F[ks & 1];
#pragma unroll
            for (int mf = 0; mf < 4; mf++)
#pragma unroll
                for (int nf = 0; nf < 4; nf++) {
                    mma16816(acc[mf][nf], f.ah[mf], f.bh[nf]);
                    mma16816(acc[mf][nf], f.al[mf], f.bh[nf]);
                }
        }
        __syncthreads();
        if (kb + 2 < KB) issue(kb + 2, st);
    }

    int g4 = lane >> 2, t4 = lane & 3;
#pragma unroll
    for (int mf = 0; mf < 4; mf++) {
        int r0 = m0 + wm * 64 + mf * 16 + g4;
#pragma unroll
        for (int nf = 0; nf < 4; nf++) {
            int cg = n0 + wn * 32 + nf * 8 + t4 * 2;
            if (cg < N) {
                float* p0 = C + (size_t)r0 * N + cg;
                p0[0] = acc[mf][nf][0];
                p0[1] = acc[mf][nf][1];
                float* p1 = p0 + (size_t)8 * N;
                p1[0] = acc[mf][nf][2];
                p1[1] = acc[mf][nf][3];
            }
        }
    }
}

__global__ __launch_bounds__(256) void gemm_in_kernel() {
    gemm_core(g_Ah, g_Al, g_Bh, g_proj, BL, ProjD, Dm);
}

__global__ __launch_bounds__(256) void gemm_out_kernel(float* __restrict__ out) {
    gemm_core(g_Ah, g_Al, g_Bh, out, BL, Dm, Inter);
}

// ---------------------------------------------------------------------------
// fp16 split conversions
// ---------------------------------------------------------------------------
__global__ void split_x_kernel(const float* __restrict__ in, int n) {
    int i = blockIdx.x * blockDim.x + threadIdx.x;
    if (i >= n) return;
    float v = in[i];
    __half h = __float2half(v);
    g_Ah[i] = h;
    g_Al[i] = __float2half(v - __half2float(h));
}

__global__ void split_w_kernel(const float* __restrict__ in, int n) {
    int i = blockIdx.x * blockDim.x + threadIdx.x;
    if (i >= n) return;
    g_Bh[i] = __float2half(in[i]);
}

// ---------------------------------------------------------------------------
// Depthwise causal conv1d + SiLU (sliding window)
// ---------------------------------------------------------------------------
__global__ __launch_bounds__(256) void conv_silu_kernel(const float* __restrict__ cw,
                                                        const float* __restrict__ cb) {
    int ch = blockIdx.x * 256 + threadIdx.x;
    int l0 = blockIdx.y * 64;
    int b  = blockIdx.z;
    const float* col = g_proj + (size_t)b * Ll * ProjD + Inter + ch;
    float w0 = cw[ch * KCONV + 0];
    float w1 = cw[ch * KCONV + 1];
    float w2 = cw[ch * KCONV + 2];
    float w3 = cw[ch * KCONV + 3];
    float bias = cb[ch];
    float xm3 = (l0 >= 3) ? col[(size_t)(l0 - 3) * ProjD] : 0.f;
    float xm2 = (l0 >= 2) ? col[(size_t)(l0 - 2) * ProjD] : 0.f;
    float xm1 = (l0 >= 1) ? col[(size_t)(l0 - 1) * ProjD] : 0.f;
    float* outp = g_conv + (size_t)(b * Ll + l0) * ConvD + ch;
#pragma unroll 4
    for (int i = 0; i < 64; i++) {
        float x0 = col[(size_t)(l0 + i) * ProjD];
        float acc = bias + w0 * xm3 + w1 * xm2 + w2 * xm1 + w3 * x0;
        outp[(size_t)i * ConvD] = siluf(acc);
        xm3 = xm2; xm2 = xm1; xm1 = x0;
    }
}

// ---------------------------------------------------------------------------
// Per-chunk inclusive cumsum of dt * A with fused softplus
// ---------------------------------------------------------------------------
__global__ void acum_kernel(const float* __restrict__ A_log,
                            const float* __restrict__ dt_bias) {
    int blk = blockIdx.x;
    int h = blk % Hh;
    int bc = blk / Hh;
    int b = bc / Nc, c = bc % Nc;
    int t = threadIdx.x;
    float A = -expf(A_log[h]);
    int bl = b * Ll + c * Ck + t;
    float raw = g_proj[(size_t)bl * ProjD + Inter + ConvD + h] + dt_bias[h];
    float dt = (raw > 20.f) ? raw : log1pf(expf(raw));
    g_dtv[(size_t)bl * Hh + h] = dt;
    float v = dt * A;
    __shared__ float s[Ck];
    s[t] = v;
    __syncthreads();
    for (int off = 1; off < Ck; off <<= 1) {
        float x = (t >= off) ? s[t - off] : 0.f;
        __syncthreads();
        s[t] += x;
        __syncthreads();
    }
    g_acum[(size_t)blk * Ck + t] = s[t];
}

// ---------------------------------------------------------------------------
// Gm[s,z] = sum_n C[s,n] * B[z,n] per (b,c), lower triangle tiles
// ---------------------------------------------------------------------------
__global__ __launch_bounds__(256) void gm_kernel() {
    int bc = blockIdx.x;
    int sT = blockIdx.y, zT = blockIdx.z;
    if (zT > sT) return;
    int b = bc / Nc, c = bc % Nc;
    int rowbase = b * Ll + c * Ck;
    __shared__ float Cs[16][65];
    __shared__ float Bs[16][65];
    int tid = threadIdx.x;
    int ty = tid >> 4, tx = tid & 15;
    float acc[4][4];
#pragma unroll
    for (int i = 0; i < 4; i++)
#pragma unroll
        for (int j = 0; j < 4; j++) acc[i][j] = 0.f;

    int lrow = tid >> 2;
    int lcol = (tid & 3) * 4;

    for (int n0 = 0; n0 < Nn; n0 += 16) {
        const float* pc = g_conv + (size_t)(rowbase + sT * 64 + lrow) * ConvD + Inter + Nn + n0 + lcol;
        const float* pb = g_conv + (size_t)(rowbase + zT * 64 + lrow) * ConvD + Inter + n0 + lcol;
#pragma unroll
        for (int u = 0; u < 4; u++) Cs[lcol + u][lrow] = pc[u];
#pragma unroll
        for (int u = 0; u < 4; u++) Bs[lcol + u][lrow] = pb[u];
        __syncthreads();
#pragma unroll
        for (int kk = 0; kk < 16; kk++) {
            float rc[4], rb[4];
#pragma unroll
            for (int i = 0; i < 4; i++) rc[i] = Cs[kk][ty * 4 + i];
#pragma unroll
            for (int j = 0; j < 4; j++) rb[j] = Bs[kk][tx * 4 + j];
#pragma unroll
            for (int i = 0; i < 4; i++)
#pragma unroll
                for (int j = 0; j < 4; j++) acc[i][j] += rc[i] * rb[j];
        }
        __syncthreads();
    }
#pragma unroll
    for (int i = 0; i < 4; i++) {
        int sg = sT * 64 + ty * 4 + i;
        float* pg = g_gm + ((size_t)bc * Ck + sg) * Ck + zT * 64 + tx * 4;
#pragma unroll
        for (int j = 0; j < 4; j++) pg[j] = acc[i][j];
    }
}

// ---------------------------------------------------------------------------
// Y_diag — R6 version (coalesced g_gm reads)
// ---------------------------------------------------------------------------
__global__ __launch_bounds__(256) void ydiag_kernel() {
    int bc = blockIdx.x;
    int h = blockIdx.y;
    int sT = blockIdx.z;
    int b = bc / Nc, c = bc % Nc;
    int tid = threadIdx.x;
    int ty = tid >> 4, tx = tid & 15;

    __shared__ float Ms[64][65];
    __shared__ float Hs[64][65];
    __shared__ float sAc[64], zAc[64];

    const float* acumC = g_acum + ((size_t)bc * Hh + h) * Ck;
    if (tid < 64) sAc[tid] = acumC[sT * 64 + tid];
    int rowbase = b * Ll + c * Ck;

    float acc[4][4];
#pragma unroll
    for (int i = 0; i < 4; i++)
#pragma unroll
        for (int j = 0; j < 4; j++) acc[i][j] = 0.f;

    for (int zT = 0; zT <= sT; zT++) {
        if (tid < 64) zAc[tid] = acumC[zT * 64 + tid];
        {
            int zz = tid >> 2;
            int p0 = (tid & 3) * 16;
            int l = rowbase + zT * 64 + zz;
            float d = g_dtv[(size_t)l * Hh + h];
            const float* ph = g_conv + (size_t)l * ConvD + h * Pp + p0;
#pragma unroll
            for (int u = 0; u < 16; u++) Hs[zz][p0 + u] = ph[u] * d;
        }
        __syncthreads();
        {
            int zz4 = (tid & 15) * 4;
            int ss4 = (tid >> 4) * 4;
            bool full = (zT < sT);
#pragma unroll
            for (int a = 0; a < 4; a++) {
                int ss = ss4 + a;
                int sg = sT * 64 + ss;
                float as = sAc[ss];
                const float* grow = g_gm + ((size_t)bc * Ck + sg) * Ck + zT * 64 + zz4;
#pragma unroll
                for (int q = 0; q < 4; q++) {
                    int zz = zz4 + q;
                    float m = 0.f;
                    if (full || (zT * 64 + zz) <= sg)
                        m = grow[q] * expf(as - zAc[zz]);
                    Ms[zz][ss] = m;
                }
            }
        }
        __syncthreads();
#pragma unroll 4
        for (int zz = 0; zz < 64; zz++) {
            float rm[4], rh[4];
#pragma unroll
            for (int i = 0; i < 4; i++) rm[i] = Ms[zz][ty * 4 + i];
#pragma unroll
            for (int j = 0; j < 4; j++) rh[j] = Hs[zz][tx * 4 + j];
#pragma unroll
            for (int i = 0; i < 4; i++)
#pragma unroll
                for (int j = 0; j < 4; j++) acc[i][j] += rm[i] * rh[j];
        }
        __syncthreads();
    }
#pragma unroll
    for (int i = 0; i < 4; i++) {
        int l = rowbase + sT * 64 + ty * 4 + i;
        float* py = g_y + (size_t)l * Inter + h * Pp + tx * 4;
#pragma unroll
        for (int j = 0; j < 4; j++) py[j] = acc[i][j];
    }
}

// ---------------------------------------------------------------------------
// states — R6 version
// ---------------------------------------------------------------------------
__global__ __launch_bounds__(256) void states_kernel() {
    int bc = blockIdx.x, h = blockIdx.y;
    int b = bc / Nc, c = bc % Nc;
    int tid = threadIdx.x;
    int ty = tid >> 4, tx = tid & 15;
    __shared__ float Hd[32][65];
    __shared__ float Bsm[32][129];
    const float* acumC = g_acum + ((size_t)bc * Hh + h) * Ck;
    float aLast = acumC[Ck - 1];
    int rowbase = b * Ll + c * Ck;
    float acc[4][8];
#pragma unroll
    for (int i = 0; i < 4; i++)
#pragma unroll
        for (int j = 0; j < 8; j++) acc[i][j] = 0.f;

    for (int l0 = 0; l0 < Ck; l0 += 32) {
        {
            int ll = tid >> 3;
            int p0 = (tid & 7) * 8;
            int l = rowbase + l0 + ll;
            float w = g_dtv[(size_t)l * Hh + h] * expf(aLast - acumC[l0 + ll]);
            const float* ph = g_conv + (size_t)l * ConvD + h * Pp + p0;
#pragma unroll
            for (int u = 0; u < 8; u++) Hd[ll][p0 + u] = ph[u] * w;
        }
        {
            int ll = tid >> 3;
            int n0v = (tid & 7) * 16;
            const float* pb = g_conv + (size_t)(rowbase + l0 + ll) * ConvD + Inter + n0v;
#pragma unroll
            for (int u = 0; u < 16; u++) Bsm[ll][n0v + u] = pb[u];
        }
        __syncthreads();
#pragma unroll 4
        for (int ll = 0; ll < 32; ll++) {
            float rh[4], rb[8];
#pragma unroll
            for (int i = 0; i < 4; i++) rh[i] = Hd[ll][ty * 4 + i];
#pragma unroll
            for (int j = 0; j < 8; j++) rb[j] = Bsm[ll][tx * 8 + j];
#pragma unroll
            for (int i = 0; i < 4; i++)
#pragma unroll
                for (int j = 0; j < 8; j++) acc[i][j] += rh[i] * rb[j];
        }
        __syncthreads();
    }
    float* ps = g_states + ((size_t)bc * Hh + h) * Pp * Nn;
#pragma unroll
    for (int i = 0; i < 4; i++)
#pragma unroll
        for (int j = 0; j < 8; j++)
            ps[(ty * 4 + i) * Nn + tx * 8 + j] = acc[i][j];
}

// ---------------------------------------------------------------------------
// Inter-chunk recurrence
// ---------------------------------------------------------------------------
__global__ void prev_kernel() {
    int idx = blockIdx.x * blockDim.x + threadIdx.x;
    if (idx >= Bb * Hh * Pp * Nn) return;
    int n = idx % Nn;
    int p = (idx / Nn) % Pp;
    int h = (idx / (Nn * Pp)) % Hh;
    int b = idx / (Nn * Pp * Hh);
    float r = 0.f;
    for (int c = 0; c < Nc; c++) {
        size_t off = (((size_t)(b * Nc + c) * Hh + h) * Pp + p) * Nn + n;
        g_prev[off] = r;
        float zl = g_acum[((size_t)(b * Nc + c) * Hh + h) * Ck + (Ck - 1)];
        r = g_states[off] + expf(zl) * r;
    }
}

// ---------------------------------------------------------------------------
// Y_off + combine — R6 version
// ---------------------------------------------------------------------------
__global__ __launch_bounds__(256) void yoff_kernel(const float* __restrict__ Dv) {
    int bc = blockIdx.x, h = blockIdx.y, lT = blockIdx.z;
    int b = bc / Nc, c = bc % Nc;
    int tid = threadIdx.x;
    int ty = tid >> 4, tx = tid & 15;
    __shared__ float Cs[16][65];
    __shared__ float Ps[16][65];
    __shared__ float lAc[64];
    const float* acumC = g_acum + ((size_t)bc * Hh + h) * Ck;
    if (tid < 64) lAc[tid] = acumC[lT * 64 + tid];
    int rowbase = b * Ll + c * Ck + lT * 64;
    const float* pprev = g_prev + ((size_t)bc * Hh + h) * Pp * Nn;

    float acc[4][4];
#pragma unroll
    for (int i = 0; i < 4; i++)
#pragma unroll
        for (int j = 0; j < 4; j++) acc[i][j] = 0.f;

    int lrow = tid >> 2;
    int lcol = (tid & 3) * 4;
    for (int n0 = 0; n0 < Nn; n0 += 16) {
        const float* pc = g_conv + (size_t)(rowbase + lrow) * ConvD + Inter + Nn + n0 + lcol;
#pragma unroll
        for (int u = 0; u < 4; u++) Cs[lcol + u][lrow] = pc[u];
        const float* pp = pprev + (size_t)lrow * Nn + n0 + lcol;
#pragma unroll
        for (int u = 0; u < 4; u++) Ps[lcol + u][lrow] = pp[u];
        __syncthreads();
#pragma unroll
        for (int kk = 0; kk < 16; kk++) {
            float rc[4], rp[4];
#pragma unroll
            for (int i = 0; i < 4; i++) rc[i] = Cs[kk][ty * 4 + i];
#pragma unroll
            for (int j = 0; j < 4; j++) rp[j] = Ps[kk][tx * 4 + j];
#pragma unroll
            for (int i = 0; i < 4; i++)
#pragma unroll
                for (int j = 0; j < 4; j++) acc[i][j] += rc[i] * rp[j];
        }
        __syncthreads();
    }
    float Dh = Dv[h];
#pragma unroll
    for (int i = 0; i < 4; i++) {
        int ll = ty * 4 + i;
        int l = rowbase + ll;
        float sd = expf(lAc[ll]);
        const float* ph = g_conv + (size_t)l * ConvD + h * Pp;
        float* py = g_y + (size_t)l * Inter + h * Pp;
#pragma unroll
        for (int j = 0; j < 4; j++) {
            int p = tx * 4 + j;
            py[p] = py[p] + acc[i][j] * sd + Dh * ph[p];
        }
    }
}

// ---------------------------------------------------------------------------
// Gated RMSNorm; writes fp16 hi/lo splits directly (fused split_y)
// ---------------------------------------------------------------------------
__global__ __launch_bounds__(256) void norm_kernel(const float* __restrict__ norm_w) {
    int row = blockIdx.x;
    int tid = threadIdx.x;
    const float* pg = g_proj + (size_t)row * ProjD;
    const float* py = g_y + (size_t)row * Inter;
    float f[8];
    float ss = 0.f;
#pragma unroll
    for (int u = 0; u < 8; u++) {
        int i = tid + u * 256;
        float g = pg[i];
        float v = py[i] * siluf(g);
        f[u] = v;
        ss += v * v;
    }
    __shared__ float red[8];
    int lane = tid & 31, wid = tid >> 5;
#pragma unroll
    for (int o = 16; o > 0; o >>= 1) ss += __shfl_xor_sync(0xffffffffu, ss, o);
    if (lane == 0) red[wid] = ss;
    __syncthreads();
    if (tid == 0) {
        float t = 0.f;
#pragma unroll
        for (int i = 0; i < 8; i++) t += red[i];
        red[0] = t;
    }
    __syncthreads();
    float rs = rsqrtf(red[0] / (float)Inter + 1e-6f);
#pragma unroll
    for (int u = 0; u < 8; u++) {
        int i = tid + u * 256;
        float v = f[u] * rs * norm_w[i];
        __half h = __float2half(v);
        size_t o = (size_t)row * Inter + i;
        g_Ah[o] = h;
        g_Al[o] = __float2half(v - __half2float(h));
    }
}

// ---------------------------------------------------------------------------
// Launch
// ---------------------------------------------------------------------------
extern "C" void kernel_launch(void* const* d_in, const int* in_sizes, int n_in,
                              void* d_out, int out_size) {
    const float* x         = (const float*)d_in[0];
    const float* in_proj_w = (const float*)d_in[1];
    const float* conv_w    = (const float*)d_in[2];
    const float* conv_b    = (const float*)d_in[3];
    const float* dt_bias   = (const float*)d_in[4];
    const float* A_log     = (const float*)d_in[5];
    const float* Dv        = (const float*)d_in[6];
    const float* norm_w    = (const float*)d_in[7];
    const float* out_proj_w= (const float*)d_in[8];
    float* out = (float*)d_out;

    cudaFuncSetAttribute(gemm_in_kernel, cudaFuncAttributeMaxDynamicSharedMemorySize, GEMM_SMEM);
    cudaFuncSetAttribute(gemm_out_kernel, cudaFuncAttributeMaxDynamicSharedMemorySize, GEMM_SMEM);

    // 1) split x (fp16 hi/lo) and round in_proj_w to fp16
    {
        int n = BL * Dm;
        split_x_kernel<<<(n + 255) / 256, 256>>>(x, n);
        n = ProjD * Dm;
        split_w_kernel<<<(n + 255) / 256, 256>>>(in_proj_w, n);
    }
    // 2) in-projection GEMM (2-pass fp16 split)
    {
        dim3 grid((ProjD + 127) / 128, BL / 128);
        gemm_in_kernel<<<grid, 256, GEMM_SMEM>>>();
    }
    // 3) conv + SiLU
    {
        dim3 grid(ConvD / 256, Ll / 64, Bb);
        conv_silu_kernel<<<grid, 256>>>(conv_w, conv_b);
    }
    // 4) cumsum of dt*A (fused softplus)
    acum_kernel<<<Bb * Nc * Hh, Ck>>>(A_log, dt_bias);
    // 5) Gm = C B^T
    {
        dim3 grid(Bb * Nc, Ck / 64, Ck / 64);
        gm_kernel<<<grid, 256>>>();
    }
    // 6) Y_diag
    {
        dim3 grid(Bb * Nc, Hh, Ck / 64);
        ydiag_kernel<<<grid, 256>>>();
    }
    // 7) states
    {
        dim3 grid(Bb * Nc, Hh);
        states_kernel<<<grid, 256>>>();
    }
    // 8) inter-chunk recurrence
    {
        int total = Bb * Hh * Pp * Nn;
        prev_kernel<<<(total + 255) / 256, 256>>>();
    }
    // 9) Y_off + combine
    {
        dim3 grid(Bb * Nc, Hh, Ck / 64);
        yoff_kernel<<<grid, 256>>>(Dv);
    }
    // 10) gated RMSNorm (writes fp16 splits)
    norm_kernel<<<BL, 256>>>(norm_w);
    // 11) round out_proj_w to fp16
    {
        int n = Dm * Inter;
        split_w_kernel<<<(n + 255) / 256, 256>>>(out_proj_w, n);
    }
    // 12) out-projection GEMM (2-pass fp16 split)
    {
        dim3 grid(Dm / 128, BL / 128);
        gemm_out_kernel<<<grid, 256, GEMM_SMEM>>>(out);
    }
    (void)in_sizes; (void)n_in; (void)out_size;
}

// round 9
// speedup vs baseline: 1.3948x; 1.1120x over previous
#include <cuda_runtime.h>
#include <cuda_fp16.h>
#include <math.h>
#include <stdint.h>

// ---------------------------------------------------------------------------
// Problem constants (fixed shapes)
// ---------------------------------------------------------------------------
#define Bb     2
#define Ll     2048
#define Dm     1024
#define Hh     32
#define Pp     64
#define Nn     128
#define KCONV  4
#define Ck     256
#define Nc     8          // Ll / Ck
#define Inter  2048
#define ConvD  2304
#define ProjD  4384
#define BL     (Bb * Ll)  // 4096

// ---------------------------------------------------------------------------
// Scratch (device globals; no dynamic allocation allowed)
// ---------------------------------------------------------------------------
__device__ float g_proj[(size_t)BL * ProjD];
__device__ float g_conv[(size_t)BL * ConvD];
__device__ float g_dtv[(size_t)BL * Hh];
__device__ float g_acum[(size_t)Bb * Nc * Hh * Ck];
__device__ float g_gm[(size_t)Bb * Nc * Ck * Ck];
__device__ float g_y[(size_t)BL * Inter];
__device__ float g_states[(size_t)Bb * Nc * Hh * Pp * Nn];
__device__ float g_prev[(size_t)Bb * Nc * Hh * Pp * Nn];

// fp16 buffers: A = Ah (+ Al for 2-pass), B rounded to fp16
__device__ __half g_Ah[(size_t)BL * Inter];
__device__ __half g_Al[(size_t)BL * Inter];
__device__ __half g_Bh[(size_t)ProjD * Dm];

__device__ __forceinline__ float siluf(float x) { return x / (1.f + expf(-x)); }

// ---------------------------------------------------------------------------
// PTX helpers
// ---------------------------------------------------------------------------
__device__ __forceinline__ unsigned su32(const void* p) {
    return (unsigned)__cvta_generic_to_shared(p);
}

__device__ __forceinline__ void cp16(unsigned dst, const void* src, bool ok) {
    int sz = ok ? 16 : 0;
    asm volatile("cp.async.cg.shared.global [%0], [%1], 16, %2;\n"
                 :: "r"(dst), "l"(src), "r"(sz));
}

__device__ __forceinline__ void ldsm4(unsigned& r0, unsigned& r1, unsigned& r2, unsigned& r3,
                                      unsigned addr) {
    asm volatile("ldmatrix.sync.aligned.m8n8.x4.shared.b16 {%0,%1,%2,%3}, [%4];"
                 : "=r"(r0), "=r"(r1), "=r"(r2), "=r"(r3) : "r"(addr));
}

__device__ __forceinline__ void mma16816(float* c, const unsigned* a, const unsigned* b) {
    asm volatile(
        "mma.sync.aligned.m16n8k16.row.col.f32.f16.f16.f32 "
        "{%0,%1,%2,%3}, {%4,%5,%6,%7}, {%8,%9}, {%0,%1,%2,%3};"
        : "+f"(c[0]), "+f"(c[1]), "+f"(c[2]), "+f"(c[3])
        : "r"(a[0]), "r"(a[1]), "r"(a[2]), "r"(a[3]), "r"(b[0]), "r"(b[1]));
}

// ---------------------------------------------------------------------------
// Tensor-core fp16 GEMM, templated pass count.
// NPASS=2: C = Ah*Bh + Al*Bh (exact-A x fp16-B). NPASS=1: C = Ah*Bh.
// Tile 128x128x64, 256 threads (8 warps: 2(m) x 4(n)), warp tile 64x32.
// smem row = 144 B; stage = (NPASS+1) mats x 128 x 144.
// ---------------------------------------------------------------------------
#define GEMM_SMEM_2P (2 * 55296)
#define GEMM_SMEM_1P (2 * 36864)

struct Frags {
    unsigned ah[4][4], al[4][4];
    unsigned bh[4][2];
};

template <int NPASS>
__device__ __forceinline__ void load_frags(Frags& F, unsigned stg, int ks,
                                           int wm, int wn, int lane) {
    constexpr unsigned BOFF = (NPASS == 1) ? 18432u : 36864u;
    const int rA = lane & 15;
    const int cB = ((lane >> 4) << 4);
    const unsigned colb = (unsigned)(ks * 32 + cB);
#pragma unroll
    for (int mf = 0; mf < 4; mf++) {
        unsigned ra = stg + (wm * 64 + mf * 16 + rA) * 144 + colb;
        ldsm4(F.ah[mf][0], F.ah[mf][1], F.ah[mf][2], F.ah[mf][3], ra);
        if (NPASS == 2)
            ldsm4(F.al[mf][0], F.al[mf][1], F.al[mf][2], F.al[mf][3], ra + 18432);
    }
#pragma unroll
    for (int nf2 = 0; nf2 < 2; nf2++) {
        unsigned rb = stg + BOFF + (wn * 32 + nf2 * 16 + rA) * 144 + colb;
        unsigned t0, t1, t2, t3;
        ldsm4(t0, t1, t2, t3, rb);
        F.bh[nf2 * 2][0] = t0; F.bh[nf2 * 2][1] = t2;
        F.bh[nf2 * 2 + 1][0] = t1; F.bh[nf2 * 2 + 1][1] = t3;
    }
}

template <int NPASS>
__device__ __forceinline__ void gemm_core(const __half* __restrict__ Ah,
                                          const __half* __restrict__ Al,
                                          const __half* __restrict__ Bh,
                                          float* __restrict__ C,
                                          int M, int N, int K) {
    extern __shared__ char dyn[];
    constexpr unsigned STG = (NPASS == 1) ? 36864u : 55296u;
    constexpr int NMAT = NPASS + 1;
    const unsigned sbase = su32(dyn);
    const int tid = threadIdx.x;
    const int lane = tid & 31;
    const int warp = tid >> 5;
    const int wm = warp >> 2;
    const int wn = warp & 3;
    const int m0 = blockIdx.y * 128;
    const int n0 = blockIdx.x * 128;
    const int KB = K >> 6;

    float acc[4][4][4];
#pragma unroll
    for (int a = 0; a < 4; a++)
#pragma unroll
        for (int b = 0; b < 4; b++)
#pragma unroll
            for (int c = 0; c < 4; c++) acc[a][b][c] = 0.f;

    auto issue = [&](int kc, int st) {
        unsigned stg = sbase + st * STG;
#pragma unroll
        for (int i = 0; i < NMAT * 4; i++) {
            int q = tid + (i << 8);
            int mat = q >> 10;                // 1p: 0=Ah,1=Bh ; 2p: 0=Ah,1=Al,2=Bh
            int r = (q >> 3) & 127;
            int c16 = q & 7;
            bool isA = (NPASS == 1) ? (mat == 0) : (mat < 2);
            const __half* base;
            if (NPASS == 1) base = mat ? Bh : Ah;
            else            base = (mat == 0) ? Ah : (mat == 1) ? Al : Bh;
            int gr = (isA ? m0 : n0) + r;
            bool ok = gr < (isA ? M : N);
            if (!ok) gr = (isA ? M : N) - 1;
            const void* src = base + (size_t)gr * K + (kc << 6) + (c16 << 3);
            unsigned dst = stg + mat * 18432 + r * 144 + (c16 << 4);
            cp16(dst, src, ok);
        }
        asm volatile("cp.async.commit_group;\n");
    };

    issue(0, 0);
    if (KB > 1) issue(1, 1);

    Frags F[2];

    for (int kb = 0; kb < KB; kb++) {
        int st = kb & 1;
        if (kb + 1 < KB) asm volatile("cp.async.wait_group 1;\n");
        else             asm volatile("cp.async.wait_group 0;\n");
        __syncthreads();
        unsigned stg = sbase + st * STG;

        load_frags<NPASS>(F[0], stg, 0, wm, wn, lane);
#pragma unroll
        for (int ks = 0; ks < 4; ks++) {
            if (ks < 3) load_frags<NPASS>(F[(ks + 1) & 1], stg, ks + 1, wm, wn, lane);
            Frags& f = F[ks & 1];
#pragma unroll
            for (int mf = 0; mf < 4; mf++)
#pragma unroll
                for (int nf = 0; nf < 4; nf++) {
                    mma16816(acc[mf][nf], f.ah[mf], f.bh[nf]);
                    if (NPASS == 2)
                        mma16816(acc[mf][nf], f.al[mf], f.bh[nf]);
                }
        }
        __syncthreads();
        if (kb + 2 < KB) issue(kb + 2, st);
    }

    int g4 = lane >> 2, t4 = lane & 3;
#pragma unroll
    for (int mf = 0; mf < 4; mf++) {
        int r0 = m0 + wm * 64 + mf * 16 + g4;
#pragma unroll
        for (int nf = 0; nf < 4; nf++) {
            int cg = n0 + wn * 32 + nf * 8 + t4 * 2;
            if (cg < N) {
                float* p0 = C + (size_t)r0 * N + cg;
                p0[0] = acc[mf][nf][0];
                p0[1] = acc[mf][nf][1];
                float* p1 = p0 + (size_t)8 * N;
                p1[0] = acc[mf][nf][2];
                p1[1] = acc[mf][nf][3];
            }
        }
    }
}

__global__ __launch_bounds__(256) void gemm_in_kernel() {
    gemm_core<1>(g_Ah, g_Al, g_Bh, g_proj, BL, ProjD, Dm);
}

__global__ __launch_bounds__(256) void gemm_out_kernel(float* __restrict__ out) {
    gemm_core<2>(g_Ah, g_Al, g_Bh, out, BL, Dm, Inter);
}

// ---------------------------------------------------------------------------
// fp16 conversions
// ---------------------------------------------------------------------------
__global__ void round_x_kernel(const float* __restrict__ in, int n) {
    int i = blockIdx.x * blockDim.x + threadIdx.x;
    if (i >= n) return;
    g_Ah[i] = __float2half(in[i]);
}

__global__ void round_w_kernel(const float* __restrict__ in, int n) {
    int i = blockIdx.x * blockDim.x + threadIdx.x;
    if (i >= n) return;
    g_Bh[i] = __float2half(in[i]);
}

// ---------------------------------------------------------------------------
// Depthwise causal conv1d + SiLU (sliding window)
// ---------------------------------------------------------------------------
__global__ __launch_bounds__(256) void conv_silu_kernel(const float* __restrict__ cw,
                                                        const float* __restrict__ cb) {
    int ch = blockIdx.x * 256 + threadIdx.x;
    int l0 = blockIdx.y * 64;
    int b  = blockIdx.z;
    const float* col = g_proj + (size_t)b * Ll * ProjD + Inter + ch;
    float w0 = cw[ch * KCONV + 0];
    float w1 = cw[ch * KCONV + 1];
    float w2 = cw[ch * KCONV + 2];
    float w3 = cw[ch * KCONV + 3];
    float bias = cb[ch];
    float xm3 = (l0 >= 3) ? col[(size_t)(l0 - 3) * ProjD] : 0.f;
    float xm2 = (l0 >= 2) ? col[(size_t)(l0 - 2) * ProjD] : 0.f;
    float xm1 = (l0 >= 1) ? col[(size_t)(l0 - 1) * ProjD] : 0.f;
    float* outp = g_conv + (size_t)(b * Ll + l0) * ConvD + ch;
#pragma unroll 4
    for (int i = 0; i < 64; i++) {
        float x0 = col[(size_t)(l0 + i) * ProjD];
        float acc = bias + w0 * xm3 + w1 * xm2 + w2 * xm1 + w3 * x0;
        outp[(size_t)i * ConvD] = siluf(acc);
        xm3 = xm2; xm2 = xm1; xm1 = x0;
    }
}

// ---------------------------------------------------------------------------
// Per-chunk inclusive cumsum of dt * A with fused softplus
// ---------------------------------------------------------------------------
__global__ void acum_kernel(const float* __restrict__ A_log,
                            const float* __restrict__ dt_bias) {
    int blk = blockIdx.x;
    int h = blk % Hh;
    int bc = blk / Hh;
    int b = bc / Nc, c = bc % Nc;
    int t = threadIdx.x;
    float A = -expf(A_log[h]);
    int bl = b * Ll + c * Ck + t;
    float raw = g_proj[(size_t)bl * ProjD + Inter + ConvD + h] + dt_bias[h];
    float dt = (raw > 20.f) ? raw : log1pf(expf(raw));
    g_dtv[(size_t)bl * Hh + h] = dt;
    float v = dt * A;
    __shared__ float s[Ck];
    s[t] = v;
    __syncthreads();
    for (int off = 1; off < Ck; off <<= 1) {
        float x = (t >= off) ? s[t - off] : 0.f;
        __syncthreads();
        s[t] += x;
        __syncthreads();
    }
    g_acum[(size_t)blk * Ck + t] = s[t];
}

// ---------------------------------------------------------------------------
// Gm[s,z] = sum_n C[s,n] * B[z,n] per (b,c), lower triangle tiles
// ---------------------------------------------------------------------------
__global__ __launch_bounds__(256) void gm_kernel() {
    int bc = blockIdx.x;
    int sT = blockIdx.y, zT = blockIdx.z;
    if (zT > sT) return;
    int b = bc / Nc, c = bc % Nc;
    int rowbase = b * Ll + c * Ck;
    __shared__ float Cs[16][65];
    __shared__ float Bs[16][65];
    int tid = threadIdx.x;
    int ty = tid >> 4, tx = tid & 15;
    float acc[4][4];
#pragma unroll
    for (int i = 0; i < 4; i++)
#pragma unroll
        for (int j = 0; j < 4; j++) acc[i][j] = 0.f;

    int lrow = tid >> 2;
    int lcol = (tid & 3) * 4;

    for (int n0 = 0; n0 < Nn; n0 += 16) {
        const float* pc = g_conv + (size_t)(rowbase + sT * 64 + lrow) * ConvD + Inter + Nn + n0 + lcol;
        const float* pb = g_conv + (size_t)(rowbase + zT * 64 + lrow) * ConvD + Inter + n0 + lcol;
#pragma unroll
        for (int u = 0; u < 4; u++) Cs[lcol + u][lrow] = pc[u];
#pragma unroll
        for (int u = 0; u < 4; u++) Bs[lcol + u][lrow] = pb[u];
        __syncthreads();
#pragma unroll
        for (int kk = 0; kk < 16; kk++) {
            float rc[4], rb[4];
#pragma unroll
            for (int i = 0; i < 4; i++) rc[i] = Cs[kk][ty * 4 + i];
#pragma unroll
            for (int j = 0; j < 4; j++) rb[j] = Bs[kk][tx * 4 + j];
#pragma unroll
            for (int i = 0; i < 4; i++)
#pragma unroll
                for (int j = 0; j < 4; j++) acc[i][j] += rc[i] * rb[j];
        }
        __syncthreads();
    }
#pragma unroll
    for (int i = 0; i < 4; i++) {
        int sg = sT * 64 + ty * 4 + i;
        float* pg = g_gm + ((size_t)bc * Ck + sg) * Ck + zT * 64 + tx * 4;
#pragma unroll
        for (int j = 0; j < 4; j++) pg[j] = acc[i][j];
    }
}

// ---------------------------------------------------------------------------
// Y_diag — coalesced g_gm reads; off-diagonal z-tiles use exp factoring:
// exp(As-Az) = exp(As-M)*exp(M-Az), M = z-tile-end cumsum (both args <= 0).
// ---------------------------------------------------------------------------
__global__ __launch_bounds__(256) void ydiag_kernel() {
    int bc = blockIdx.x;
    int h = blockIdx.y;
    int sT = blockIdx.z;
    int b = bc / Nc, c = bc % Nc;
    int tid = threadIdx.x;
    int ty = tid >> 4, tx = tid & 15;

    __shared__ float Ms[64][65];
    __shared__ float Hs[64][65];
    __shared__ float sAc[64], zAc[64], ezs[64];

    const float* acumC = g_acum + ((size_t)bc * Hh + h) * Ck;
    if (tid < 64) sAc[tid] = acumC[sT * 64 + tid];
    int rowbase = b * Ll + c * Ck;

    float acc[4][4];
#pragma unroll
    for (int i = 0; i < 4; i++)
#pragma unroll
        for (int j = 0; j < 4; j++) acc[i][j] = 0.f;

    for (int zT = 0; zT <= sT; zT++) {
        float M = acumC[zT * 64 + 63];
        if (tid < 64) {
            float az = acumC[zT * 64 + tid];
            zAc[tid] = az;
            ezs[tid] = expf(M - az);
        }
        {
            int zz = tid >> 2;
            int p0 = (tid & 3) * 16;
            int l = rowbase + zT * 64 + zz;
            float d = g_dtv[(size_t)l * Hh + h];
            const float* ph = g_conv + (size_t)l * ConvD + h * Pp + p0;
#pragma unroll
            for (int u = 0; u < 16; u++) Hs[zz][p0 + u] = ph[u] * d;
        }
        __syncthreads();
        {
            int zz4 = (tid & 15) * 4;
            int ss4 = (tid >> 4) * 4;
            if (zT < sT) {
#pragma unroll
                for (int a = 0; a < 4; a++) {
                    int ss = ss4 + a;
                    int sg = sT * 64 + ss;
                    float es = expf(sAc[ss] - M);
                    const float* grow = g_gm + ((size_t)bc * Ck + sg) * Ck + zT * 64 + zz4;
#pragma unroll
                    for (int q = 0; q < 4; q++)
                        Ms[zz4 + q][ss] = grow[q] * ezs[zz4 + q] * es;
                }
            } else {
#pragma unroll
                for (int a = 0; a < 4; a++) {
                    int ss = ss4 + a;
                    int sg = sT * 64 + ss;
                    float as = sAc[ss];
                    const float* grow = g_gm + ((size_t)bc * Ck + sg) * Ck + zT * 64 + zz4;
#pragma unroll
                    for (int q = 0; q < 4; q++) {
                        int zz = zz4 + q;
                        float m = 0.f;
                        if ((zT * 64 + zz) <= sg)
                            m = grow[q] * expf(as - zAc[zz]);
                        Ms[zz][ss] = m;
                    }
                }
            }
        }
        __syncthreads();
#pragma unroll 4
        for (int zz = 0; zz < 64; zz++) {
            float rm[4], rh[4];
#pragma unroll
            for (int i = 0; i < 4; i++) rm[i] = Ms[zz][ty * 4 + i];
#pragma unroll
            for (int j = 0; j < 4; j++) rh[j] = Hs[zz][tx * 4 + j];
#pragma unroll
            for (int i = 0; i < 4; i++)
#pragma unroll
                for (int j = 0; j < 4; j++) acc[i][j] += rm[i] * rh[j];
        }
        __syncthreads();
    }
#pragma unroll
    for (int i = 0; i < 4; i++) {
        int l = rowbase + sT * 64 + ty * 4 + i;
        float* py = g_y + (size_t)l * Inter + h * Pp + tx * 4;
#pragma unroll
        for (int j = 0; j < 4; j++) py[j] = acc[i][j];
    }
}

// ---------------------------------------------------------------------------
// states
// ---------------------------------------------------------------------------
__global__ __launch_bounds__(256) void states_kernel() {
    int bc = blockIdx.x, h = blockIdx.y;
    int b = bc / Nc, c = bc % Nc;
    int tid = threadIdx.x;
    int ty = tid >> 4, tx = tid & 15;
    __shared__ float Hd[32][65];
    __shared__ float Bsm[32][129];
    const float* acumC = g_acum + ((size_t)bc * Hh + h) * Ck;
    float aLast = acumC[Ck - 1];
    int rowbase = b * Ll + c * Ck;
    float acc[4][8];
#pragma unroll
    for (int i = 0; i < 4; i++)
#pragma unroll
        for (int j = 0; j < 8; j++) acc[i][j] = 0.f;

    for (int l0 = 0; l0 < Ck; l0 += 32) {
        {
            int ll = tid >> 3;
            int p0 = (tid & 7) * 8;
            int l = rowbase + l0 + ll;
            float w = g_dtv[(size_t)l * Hh + h] * expf(aLast - acumC[l0 + ll]);
            const float* ph = g_conv + (size_t)l * ConvD + h * Pp + p0;
#pragma unroll
            for (int u = 0; u < 8; u++) Hd[ll][p0 + u] = ph[u] * w;
        }
        {
            int ll = tid >> 3;
            int n0v = (tid & 7) * 16;
            const float* pb = g_conv + (size_t)(rowbase + l0 + ll) * ConvD + Inter + n0v;
#pragma unroll
            for (int u = 0; u < 16; u++) Bsm[ll][n0v + u] = pb[u];
        }
        __syncthreads();
#pragma unroll 4
        for (int ll = 0; ll < 32; ll++) {
            float rh[4], rb[8];
#pragma unroll
            for (int i = 0; i < 4; i++) rh[i] = Hd[ll][ty * 4 + i];
#pragma unroll
            for (int j = 0; j < 8; j++) rb[j] = Bsm[ll][tx * 8 + j];
#pragma unroll
            for (int i = 0; i < 4; i++)
#pragma unroll
                for (int j = 0; j < 8; j++) acc[i][j] += rh[i] * rb[j];
        }
        __syncthreads();
    }
    float* ps = g_states + ((size_t)bc * Hh + h) * Pp * Nn;
#pragma unroll
    for (int i = 0; i < 4; i++)
#pragma unroll
        for (int j = 0; j < 8; j++)
            ps[(ty * 4 + i) * Nn + tx * 8 + j] = acc[i][j];
}

// ---------------------------------------------------------------------------
// Inter-chunk recurrence
// ---------------------------------------------------------------------------
__global__ void prev_kernel() {
    int idx = blockIdx.x * blockDim.x + threadIdx.x;
    if (idx >= Bb * Hh * Pp * Nn) return;
    int n = idx % Nn;
    int p = (idx / Nn) % Pp;
    int h = (idx / (Nn * Pp)) % Hh;
    int b = idx / (Nn * Pp * Hh);
    float r = 0.f;
    for (int c = 0; c < Nc; c++) {
        size_t off = (((size_t)(b * Nc + c) * Hh + h) * Pp + p) * Nn + n;
        g_prev[off] = r;
        float zl = g_acum[((size_t)(b * Nc + c) * Hh + h) * Ck + (Ck - 1)];
        r = g_states[off] + expf(zl) * r;
    }
}

// ---------------------------------------------------------------------------
// Y_off + combine
// ---------------------------------------------------------------------------
__global__ __launch_bounds__(256) void yoff_kernel(const float* __restrict__ Dv) {
    int bc = blockIdx.x, h = blockIdx.y, lT = blockIdx.z;
    int b = bc / Nc, c = bc % Nc;
    int tid = threadIdx.x;
    int ty = tid >> 4, tx = tid & 15;
    __shared__ float Cs[16][65];
    __shared__ float Ps[16][65];
    __shared__ float lAc[64];
    const float* acumC = g_acum + ((size_t)bc * Hh + h) * Ck;
    if (tid < 64) lAc[tid] = acumC[lT * 64 + tid];
    int rowbase = b * Ll + c * Ck + lT * 64;
    const float* pprev = g_prev + ((size_t)bc * Hh + h) * Pp * Nn;

    float acc[4][4];
#pragma unroll
    for (int i = 0; i < 4; i++)
#pragma unroll
        for (int j = 0; j < 4; j++) acc[i][j] = 0.f;

    int lrow = tid >> 2;
    int lcol = (tid & 3) * 4;
    for (int n0 = 0; n0 < Nn; n0 += 16) {
        const float* pc = g_conv + (size_t)(rowbase + lrow) * ConvD + Inter + Nn + n0 + lcol;
#pragma unroll
        for (int u = 0; u < 4; u++) Cs[lcol + u][lrow] = pc[u];
        const float* pp = pprev + (size_t)lrow * Nn + n0 + lcol;
#pragma unroll
        for (int u = 0; u < 4; u++) Ps[lcol + u][lrow] = pp[u];
        __syncthreads();
#pragma unroll
        for (int kk = 0; kk < 16; kk++) {
            float rc[4], rp[4];
#pragma unroll
            for (int i = 0; i < 4; i++) rc[i] = Cs[kk][ty * 4 + i];
#pragma unroll
            for (int j = 0; j < 4; j++) rp[j] = Ps[kk][tx * 4 + j];
#pragma unroll
            for (int i = 0; i < 4; i++)
#pragma unroll
                for (int j = 0; j < 4; j++) acc[i][j] += rc[i] * rp[j];
        }
        __syncthreads();
    }
    float Dh = Dv[h];
#pragma unroll
    for (int i = 0; i < 4; i++) {
        int ll = ty * 4 + i;
        int l = rowbase + ll;
        float sd = expf(lAc[ll]);
        const float* ph = g_conv + (size_t)l * ConvD + h * Pp;
        float* py = g_y + (size_t)l * Inter + h * Pp;
#pragma unroll
        for (int j = 0; j < 4; j++) {
            int p = tx * 4 + j;
            py[p] = py[p] + acc[i][j] * sd + Dh * ph[p];
        }
    }
}

// ---------------------------------------------------------------------------
// Gated RMSNorm; writes fp16 hi/lo splits for the 2-pass out-proj
// ---------------------------------------------------------------------------
__global__ __launch_bounds__(256) void norm_kernel(const float* __restrict__ norm_w) {
    int row = blockIdx.x;
    int tid = threadIdx.x;
    const float* pg = g_proj + (size_t)row * ProjD;
    const float* py = g_y + (size_t)row * Inter;
    float f[8];
    float ss = 0.f;
#pragma unroll
    for (int u = 0; u < 8; u++) {
        int i = tid + u * 256;
        float g = pg[i];
        float v = py[i] * siluf(g);
        f[u] = v;
        ss += v * v;
    }
    __shared__ float red[8];
    int lane = tid & 31, wid = tid >> 5;
#pragma unroll
    for (int o = 16; o > 0; o >>= 1) ss += __shfl_xor_sync(0xffffffffu, ss, o);
    if (lane == 0) red[wid] = ss;
    __syncthreads();
    if (tid == 0) {
        float t = 0.f;
#pragma unroll
        for (int i = 0; i < 8; i++) t += red[i];
        red[0] = t;
    }
    __syncthreads();
    float rs = rsqrtf(red[0] / (float)Inter + 1e-6f);
#pragma unroll
    for (int u = 0; u < 8; u++) {
        int i = tid + u * 256;
        float v = f[u] * rs * norm_w[i];
        __half h = __float2half(v);
        size_t o = (size_t)row * Inter + i;
        g_Ah[o] = h;
        g_Al[o] = __float2half(v - __half2float(h));
    }
}

// ---------------------------------------------------------------------------
// Launch
// ---------------------------------------------------------------------------
extern "C" void kernel_launch(void* const* d_in, const int* in_sizes, int n_in,
                              void* d_out, int out_size) {
    const float* x         = (const float*)d_in[0];
    const float* in_proj_w = (const float*)d_in[1];
    const float* conv_w    = (const float*)d_in[2];
    const float* conv_b    = (const float*)d_in[3];
    const float* dt_bias   = (const float*)d_in[4];
    const float* A_log     = (const float*)d_in[5];
    const float* Dv        = (const float*)d_in[6];
    const float* norm_w    = (const float*)d_in[7];
    const float* out_proj_w= (const float*)d_in[8];
    float* out = (float*)d_out;

    cudaFuncSetAttribute(gemm_in_kernel, cudaFuncAttributeMaxDynamicSharedMemorySize, GEMM_SMEM_1P);
    cudaFuncSetAttribute(gemm_out_kernel, cudaFuncAttributeMaxDynamicSharedMemorySize, GEMM_SMEM_2P);

    // 1) round x and in_proj_w to fp16
    {
        int n = BL * Dm;
        round_x_kernel<<<(n + 255) / 256, 256>>>(x, n);
        n = ProjD * Dm;
        round_w_kernel<<<(n + 255) / 256, 256>>>(in_proj_w, n);
    }
    // 2) in-projection GEMM (1-pass fp16)
    {
        dim3 grid((ProjD + 127) / 128, BL / 128);
        gemm_in_kernel<<<grid, 256, GEMM_SMEM_1P>>>();
    }
    // 3) conv + SiLU
    {
        dim3 grid(ConvD / 256, Ll / 64, Bb);
        conv_silu_kernel<<<grid, 256>>>(conv_w, conv_b);
    }
    // 4) cumsum of dt*A (fused softplus)
    acum_kernel<<<Bb * Nc * Hh, Ck>>>(A_log, dt_bias);
    // 5) Gm = C B^T
    {
        dim3 grid(Bb * Nc, Ck / 64, Ck / 64);
        gm_kernel<<<grid, 256>>>();
    }
    // 6) Y_diag (off-diag exp factoring)
    {
        dim3 grid(Bb * Nc, Hh, Ck / 64);
        ydiag_kernel<<<grid, 256>>>();
    }
    // 7) states
    {
        dim3 grid(Bb * Nc, Hh);
        states_kernel<<<grid, 256>>>();
    }
    // 8) inter-chunk recurrence
    {
        int total = Bb * Hh * Pp * Nn;
        prev_kernel<<<(total + 255) / 256, 256>>>();
    }
    // 9) Y_off + combine
    {
        dim3 grid(Bb * Nc, Hh, Ck / 64);
        yoff_kernel<<<grid, 256>>>(Dv);
    }
    // 10) gated RMSNorm (writes fp16 splits)
    norm_kernel<<<BL, 256>>>(norm_w);
    // 11) round out_proj_w to fp16
    {
        int n = Dm * Inter;
        round_w_kernel<<<(n + 255) / 256, 256>>>(out_proj_w, n);
    }
    // 12) out-projection GEMM (2-pass fp16 split)
    {
        dim3 grid(Dm / 128, BL / 128);
        gemm_out_kernel<<<grid, 256, GEMM_SMEM_2P>>>(out);
    }
    (void)in_sizes; (void)n_in; (void)out_size;
}

// round 10
// speedup vs baseline: 1.5078x; 1.0810x over previous
#include <cuda_runtime.h>
#include <cuda_fp16.h>
#include <math.h>
#include <stdint.h>

// ---------------------------------------------------------------------------
// Problem constants (fixed shapes)
// ---------------------------------------------------------------------------
#define Bb     2
#define Ll     2048
#define Dm     1024
#define Hh     32
#define Pp     64
#define Nn     128
#define KCONV  4
#define Ck     256
#define Nc     8          // Ll / Ck
#define Inter  2048
#define ConvD  2304
#define ProjD  4384
#define BL     (Bb * Ll)  // 4096

// ---------------------------------------------------------------------------
// Scratch (device globals; no dynamic allocation allowed)
// ---------------------------------------------------------------------------
__device__ float g_proj[(size_t)BL * ProjD];
__device__ float g_conv[(size_t)BL * ConvD];
__device__ float g_dtv[(size_t)BL * Hh];
__device__ float g_acum[(size_t)Bb * Nc * Hh * Ck];
__device__ float g_gm[(size_t)Bb * Nc * Ck * Ck];
__device__ float g_y[(size_t)BL * Inter];
__device__ float g_states[(size_t)Bb * Nc * Hh * Pp * Nn];
__device__ float g_prev[(size_t)Bb * Nc * Hh * Pp * Nn];

// fp16 buffers
__device__ __half g_Ah[(size_t)BL * Inter];
__device__ __half g_Bh[(size_t)ProjD * Dm];

__device__ __forceinline__ float siluf(float x) { return x / (1.f + expf(-x)); }

// ---------------------------------------------------------------------------
// PTX helpers
// ---------------------------------------------------------------------------
__device__ __forceinline__ unsigned su32(const void* p) {
    return (unsigned)__cvta_generic_to_shared(p);
}

__device__ __forceinline__ void cp16(unsigned dst, const void* src, bool ok) {
    int sz = ok ? 16 : 0;
    asm volatile("cp.async.cg.shared.global [%0], [%1], 16, %2;\n"
                 :: "r"(dst), "l"(src), "r"(sz));
}

__device__ __forceinline__ void ldsm4(unsigned& r0, unsigned& r1, unsigned& r2, unsigned& r3,
                                      unsigned addr) {
    asm volatile("ldmatrix.sync.aligned.m8n8.x4.shared.b16 {%0,%1,%2,%3}, [%4];"
                 : "=r"(r0), "=r"(r1), "=r"(r2), "=r"(r3) : "r"(addr));
}

__device__ __forceinline__ void mma16816(float* c, const unsigned* a, const unsigned* b) {
    asm volatile(
        "mma.sync.aligned.m16n8k16.row.col.f32.f16.f16.f32 "
        "{%0,%1,%2,%3}, {%4,%5,%6,%7}, {%8,%9}, {%0,%1,%2,%3};"
        : "+f"(c[0]), "+f"(c[1]), "+f"(c[2]), "+f"(c[3])
        : "r"(a[0]), "r"(a[1]), "r"(a[2]), "r"(a[3]), "r"(b[0]), "r"(b[1]));
}

// ---------------------------------------------------------------------------
// Tensor-core fp16 GEMM, 1-pass: C = Ah*Bh (both fp16-rounded), fp32 accum.
// Tile 128x128x64, 256 threads (8 warps: 2(m) x 4(n)), warp tile 64x32.
// smem row = 144 B; stage = 2 mats x 128 x 144 = 36864 B; 2 stages.
// ---------------------------------------------------------------------------
#define GEMM_SMEM (2 * 36864)

struct Frags {
    unsigned ah[4][4];
    unsigned bh[4][2];
};

__device__ __forceinline__ void load_frags(Frags& F, unsigned stg, int ks,
                                           int wm, int wn, int lane) {
    const int rA = lane & 15;
    const int cB = ((lane >> 4) << 4);
    const unsigned colb = (unsigned)(ks * 32 + cB);
#pragma unroll
    for (int mf = 0; mf < 4; mf++) {
        unsigned ra = stg + (wm * 64 + mf * 16 + rA) * 144 + colb;
        ldsm4(F.ah[mf][0], F.ah[mf][1], F.ah[mf][2], F.ah[mf][3], ra);
    }
#pragma unroll
    for (int nf2 = 0; nf2 < 2; nf2++) {
        unsigned rb = stg + 18432 + (wn * 32 + nf2 * 16 + rA) * 144 + colb;
        unsigned t0, t1, t2, t3;
        ldsm4(t0, t1, t2, t3, rb);
        F.bh[nf2 * 2][0] = t0; F.bh[nf2 * 2][1] = t2;
        F.bh[nf2 * 2 + 1][0] = t1; F.bh[nf2 * 2 + 1][1] = t3;
    }
}

__device__ __forceinline__ void gemm_core(const __half* __restrict__ Ah,
                                          const __half* __restrict__ Bh,
                                          float* __restrict__ C,
                                          int M, int N, int K) {
    extern __shared__ char dyn[];
    const unsigned sbase = su32(dyn);
    const int tid = threadIdx.x;
    const int lane = tid & 31;
    const int warp = tid >> 5;
    const int wm = warp >> 2;
    const int wn = warp & 3;
    const int m0 = blockIdx.y * 128;
    const int n0 = blockIdx.x * 128;
    const int KB = K >> 6;

    float acc[4][4][4];
#pragma unroll
    for (int a = 0; a < 4; a++)
#pragma unroll
        for (int b = 0; b < 4; b++)
#pragma unroll
            for (int c = 0; c < 4; c++) acc[a][b][c] = 0.f;

    auto issue = [&](int kc, int st) {
        unsigned stg = sbase + st * 36864;
#pragma unroll
        for (int i = 0; i < 8; i++) {
            int q = tid + (i << 8);           // 0..2047
            int mat = q >> 10;                // 0:Ah 1:Bh
            int r = (q >> 3) & 127;
            int c16 = q & 7;
            const __half* base = mat ? Bh : Ah;
            int gr = (mat ? n0 : m0) + r;
            bool ok = gr < (mat ? N : M);
            if (!ok) gr = (mat ? N : M) - 1;
            const void* src = base + (size_t)gr * K + (kc << 6) + (c16 << 3);
            unsigned dst = stg + mat * 18432 + r * 144 + (c16 << 4);
            cp16(dst, src, ok);
        }
        asm volatile("cp.async.commit_group;\n");
    };

    issue(0, 0);
    if (KB > 1) issue(1, 1);

    Frags F[2];

    for (int kb = 0; kb < KB; kb++) {
        int st = kb & 1;
        if (kb + 1 < KB) asm volatile("cp.async.wait_group 1;\n");
        else             asm volatile("cp.async.wait_group 0;\n");
        __syncthreads();
        unsigned stg = sbase + st * 36864;

        load_frags(F[0], stg, 0, wm, wn, lane);
#pragma unroll
        for (int ks = 0; ks < 4; ks++) {
            if (ks < 3) load_frags(F[(ks + 1) & 1], stg, ks + 1, wm, wn, lane);
            Frags& f = F[ks & 1];
#pragma unroll
            for (int mf = 0; mf < 4; mf++)
#pragma unroll
                for (int nf = 0; nf < 4; nf++)
                    mma16816(acc[mf][nf], f.ah[mf], f.bh[nf]);
        }
        __syncthreads();
        if (kb + 2 < KB) issue(kb + 2, st);
    }

    int g4 = lane >> 2, t4 = lane & 3;
#pragma unroll
    for (int mf = 0; mf < 4; mf++) {
        int r0 = m0 + wm * 64 + mf * 16 + g4;
#pragma unroll
        for (int nf = 0; nf < 4; nf++) {
            int cg = n0 + wn * 32 + nf * 8 + t4 * 2;
            if (cg < N) {
                float* p0 = C + (size_t)r0 * N + cg;
                p0[0] = acc[mf][nf][0];
                p0[1] = acc[mf][nf][1];
                float* p1 = p0 + (size_t)8 * N;
                p1[0] = acc[mf][nf][2];
                p1[1] = acc[mf][nf][3];
            }
        }
    }
}

__global__ __launch_bounds__(256) void gemm_in_kernel() {
    gemm_core(g_Ah, g_Bh, g_proj, BL, ProjD, Dm);
}

__global__ __launch_bounds__(256) void gemm_out_kernel(float* __restrict__ out) {
    gemm_core(g_Ah, g_Bh, out, BL, Dm, Inter);
}

// ---------------------------------------------------------------------------
// fp16 conversions
// ---------------------------------------------------------------------------
__global__ void round_x_kernel(const float* __restrict__ in, int n) {
    int i = blockIdx.x * blockDim.x + threadIdx.x;
    if (i >= n) return;
    g_Ah[i] = __float2half(in[i]);
}

__global__ void round_w_kernel(const float* __restrict__ in, int n) {
    int i = blockIdx.x * blockDim.x + threadIdx.x;
    if (i >= n) return;
    g_Bh[i] = __float2half(in[i]);
}

// ---------------------------------------------------------------------------
// Depthwise causal conv1d + SiLU (sliding window, 32 positions/thread)
// grid: (ConvD/256, Ll/32, Bb)
// ---------------------------------------------------------------------------
__global__ __launch_bounds__(256) void conv_silu_kernel(const float* __restrict__ cw,
                                                        const float* __restrict__ cb) {
    int ch = blockIdx.x * 256 + threadIdx.x;
    int l0 = blockIdx.y * 32;
    int b  = blockIdx.z;
    const float* col = g_proj + (size_t)b * Ll * ProjD + Inter + ch;
    float w0 = cw[ch * KCONV + 0];
    float w1 = cw[ch * KCONV + 1];
    float w2 = cw[ch * KCONV + 2];
    float w3 = cw[ch * KCONV + 3];
    float bias = cb[ch];
    float xm3 = (l0 >= 3) ? col[(size_t)(l0 - 3) * ProjD] : 0.f;
    float xm2 = (l0 >= 2) ? col[(size_t)(l0 - 2) * ProjD] : 0.f;
    float xm1 = (l0 >= 1) ? col[(size_t)(l0 - 1) * ProjD] : 0.f;
    float* outp = g_conv + (size_t)(b * Ll + l0) * ConvD + ch;
#pragma unroll 4
    for (int i = 0; i < 32; i++) {
        float x0 = col[(size_t)(l0 + i) * ProjD];
        float acc = bias + w0 * xm3 + w1 * xm2 + w2 * xm1 + w3 * x0;
        outp[(size_t)i * ConvD] = siluf(acc);
        xm3 = xm2; xm2 = xm1; xm1 = x0;
    }
}

// ---------------------------------------------------------------------------
// Per-chunk inclusive cumsum of dt * A with fused softplus
// ---------------------------------------------------------------------------
__global__ void acum_kernel(const float* __restrict__ A_log,
                            const float* __restrict__ dt_bias) {
    int blk = blockIdx.x;
    int h = blk % Hh;
    int bc = blk / Hh;
    int b = bc / Nc, c = bc % Nc;
    int t = threadIdx.x;
    float A = -expf(A_log[h]);
    int bl = b * Ll + c * Ck + t;
    float raw = g_proj[(size_t)bl * ProjD + Inter + ConvD + h] + dt_bias[h];
    float dt = (raw > 20.f) ? raw : log1pf(expf(raw));
    g_dtv[(size_t)bl * Hh + h] = dt;
    float v = dt * A;
    __shared__ float s[Ck];
    s[t] = v;
    __syncthreads();
    for (int off = 1; off < Ck; off <<= 1) {
        float x = (t >= off) ? s[t - off] : 0.f;
        __syncthreads();
        s[t] += x;
        __syncthreads();
    }
    g_acum[(size_t)blk * Ck + t] = s[t];
}

// ---------------------------------------------------------------------------
// Gm[s,z] = sum_n C[s,n] * B[z,n] per (b,c), lower triangle tiles
// ---------------------------------------------------------------------------
__global__ __launch_bounds__(256) void gm_kernel() {
    int bc = blockIdx.x;
    int sT = blockIdx.y, zT = blockIdx.z;
    if (zT > sT) return;
    int b = bc / Nc, c = bc % Nc;
    int rowbase = b * Ll + c * Ck;
    __shared__ float Cs[16][65];
    __shared__ float Bs[16][65];
    int tid = threadIdx.x;
    int ty = tid >> 4, tx = tid & 15;
    float acc[4][4];
#pragma unroll
    for (int i = 0; i < 4; i++)
#pragma unroll
        for (int j = 0; j < 4; j++) acc[i][j] = 0.f;

    int lrow = tid >> 2;
    int lcol = (tid & 3) * 4;

    for (int n0 = 0; n0 < Nn; n0 += 16) {
        const float* pc = g_conv + (size_t)(rowbase + sT * 64 + lrow) * ConvD + Inter + Nn + n0 + lcol;
        const float* pb = g_conv + (size_t)(rowbase + zT * 64 + lrow) * ConvD + Inter + n0 + lcol;
#pragma unroll
        for (int u = 0; u < 4; u++) Cs[lcol + u][lrow] = pc[u];
#pragma unroll
        for (int u = 0; u < 4; u++) Bs[lcol + u][lrow] = pb[u];
        __syncthreads();
#pragma unroll
        for (int kk = 0; kk < 16; kk++) {
            float rc[4], rb[4];
#pragma unroll
            for (int i = 0; i < 4; i++) rc[i] = Cs[kk][ty * 4 + i];
#pragma unroll
            for (int j = 0; j < 4; j++) rb[j] = Bs[kk][tx * 4 + j];
#pragma unroll
            for (int i = 0; i < 4; i++)
#pragma unroll
                for (int j = 0; j < 4; j++) acc[i][j] += rc[i] * rb[j];
        }
        __syncthreads();
    }
#pragma unroll
    for (int i = 0; i < 4; i++) {
        int sg = sT * 64 + ty * 4 + i;
        float* pg = g_gm + ((size_t)bc * Ck + sg) * Ck + zT * 64 + tx * 4;
#pragma unroll
        for (int j = 0; j < 4; j++) pg[j] = acc[i][j];
    }
}

// ---------------------------------------------------------------------------
// Y_diag — coalesced g_gm reads; off-diagonal z-tiles use exp factoring
// ---------------------------------------------------------------------------
__global__ __launch_bounds__(256) void ydiag_kernel() {
    int bc = blockIdx.x;
    int h = blockIdx.y;
    int sT = blockIdx.z;
    int b = bc / Nc, c = bc % Nc;
    int tid = threadIdx.x;
    int ty = tid >> 4, tx = tid & 15;

    __shared__ float Ms[64][65];
    __shared__ float Hs[64][65];
    __shared__ float sAc[64], zAc[64], ezs[64];

    const float* acumC = g_acum + ((size_t)bc * Hh + h) * Ck;
    if (tid < 64) sAc[tid] = acumC[sT * 64 + tid];
    int rowbase = b * Ll + c * Ck;

    float acc[4][4];
#pragma unroll
    for (int i = 0; i < 4; i++)
#pragma unroll
        for (int j = 0; j < 4; j++) acc[i][j] = 0.f;

    for (int zT = 0; zT <= sT; zT++) {
        float M = acumC[zT * 64 + 63];
        if (tid < 64) {
            float az = acumC[zT * 64 + tid];
            zAc[tid] = az;
            ezs[tid] = expf(M - az);
        }
        {
            int zz = tid >> 2;
            int p0 = (tid & 3) * 16;
            int l = rowbase + zT * 64 + zz;
            float d = g_dtv[(size_t)l * Hh + h];
            const float* ph = g_conv + (size_t)l * ConvD + h * Pp + p0;
#pragma unroll
            for (int u = 0; u < 16; u++) Hs[zz][p0 + u] = ph[u] * d;
        }
        __syncthreads();
        {
            int zz4 = (tid & 15) * 4;
            int ss4 = (tid >> 4) * 4;
            if (zT < sT) {
#pragma unroll
                for (int a = 0; a < 4; a++) {
                    int ss = ss4 + a;
                    int sg = sT * 64 + ss;
                    float es = expf(sAc[ss] - M);
                    const float* grow = g_gm + ((size_t)bc * Ck + sg) * Ck + zT * 64 + zz4;
#pragma unroll
                    for (int q = 0; q < 4; q++)
                        Ms[zz4 + q][ss] = grow[q] * ezs[zz4 + q] * es;
                }
            } else {
#pragma unroll
                for (int a = 0; a < 4; a++) {
                    int ss = ss4 + a;
                    int sg = sT * 64 + ss;
                    float as = sAc[ss];
                    const float* grow = g_gm + ((size_t)bc * Ck + sg) * Ck + zT * 64 + zz4;
#pragma unroll
                    for (int q = 0; q < 4; q++) {
                        int zz = zz4 + q;
                        float m = 0.f;
                        if ((zT * 64 + zz) <= sg)
                            m = grow[q] * expf(as - zAc[zz]);
                        Ms[zz][ss] = m;
                    }
                }
            }
        }
        __syncthreads();
#pragma unroll 4
        for (int zz = 0; zz < 64; zz++) {
            float rm[4], rh[4];
#pragma unroll
            for (int i = 0; i < 4; i++) rm[i] = Ms[zz][ty * 4 + i];
#pragma unroll
            for (int j = 0; j < 4; j++) rh[j] = Hs[zz][tx * 4 + j];
#pragma unroll
            for (int i = 0; i < 4; i++)
#pragma unroll
                for (int j = 0; j < 4; j++) acc[i][j] += rm[i] * rh[j];
        }
        __syncthreads();
    }
#pragma unroll
    for (int i = 0; i < 4; i++) {
        int l = rowbase + sT * 64 + ty * 4 + i;
        float* py = g_y + (size_t)l * Inter + h * Pp + tx * 4;
#pragma unroll
        for (int j = 0; j < 4; j++) py[j] = acc[i][j];
    }
}

// ---------------------------------------------------------------------------
// states
// ---------------------------------------------------------------------------
__global__ __launch_bounds__(256) void states_kernel() {
    int bc = blockIdx.x, h = blockIdx.y;
    int b = bc / Nc, c = bc % Nc;
    int tid = threadIdx.x;
    int ty = tid >> 4, tx = tid & 15;
    __shared__ float Hd[32][65];
    __shared__ float Bsm[32][129];
    const float* acumC = g_acum + ((size_t)bc * Hh + h) * Ck;
    float aLast = acumC[Ck - 1];
    int rowbase = b * Ll + c * Ck;
    float acc[4][8];
#pragma unroll
    for (int i = 0; i < 4; i++)
#pragma unroll
        for (int j = 0; j < 8; j++) acc[i][j] = 0.f;

    for (int l0 = 0; l0 < Ck; l0 += 32) {
        {
            int ll = tid >> 3;
            int p0 = (tid & 7) * 8;
            int l = rowbase + l0 + ll;
            float w = g_dtv[(size_t)l * Hh + h] * expf(aLast - acumC[l0 + ll]);
            const float* ph = g_conv + (size_t)l * ConvD + h * Pp + p0;
#pragma unroll
            for (int u = 0; u < 8; u++) Hd[ll][p0 + u] = ph[u] * w;
        }
        {
            int ll = tid >> 3;
            int n0v = (tid & 7) * 16;
            const float* pb = g_conv + (size_t)(rowbase + l0 + ll) * ConvD + Inter + n0v;
#pragma unroll
            for (int u = 0; u < 16; u++) Bsm[ll][n0v + u] = pb[u];
        }
        __syncthreads();
#pragma unroll 4
        for (int ll = 0; ll < 32; ll++) {
            float rh[4], rb[8];
#pragma unroll
            for (int i = 0; i < 4; i++) rh[i] = Hd[ll][ty * 4 + i];
#pragma unroll
            for (int j = 0; j < 8; j++) rb[j] = Bsm[ll][tx * 8 + j];
#pragma unroll
            for (int i = 0; i < 4; i++)
#pragma unroll
                for (int j = 0; j < 8; j++) acc[i][j] += rh[i] * rb[j];
        }
        __syncthreads();
    }
    float* ps = g_states + ((size_t)bc * Hh + h) * Pp * Nn;
#pragma unroll
    for (int i = 0; i < 4; i++)
#pragma unroll
        for (int j = 0; j < 8; j++)
            ps[(ty * 4 + i) * Nn + tx * 8 + j] = acc[i][j];
}

// ---------------------------------------------------------------------------
// Inter-chunk recurrence
// ---------------------------------------------------------------------------
__global__ void prev_kernel() {
    int idx = blockIdx.x * blockDim.x + threadIdx.x;
    if (idx >= Bb * Hh * Pp * Nn) return;
    int n = idx % Nn;
    int p = (idx / Nn) % Pp;
    int h = (idx / (Nn * Pp)) % Hh;
    int b = idx / (Nn * Pp * Hh);
    float r = 0.f;
    for (int c = 0; c < Nc; c++) {
        size_t off = (((size_t)(b * Nc + c) * Hh + h) * Pp + p) * Nn + n;
        g_prev[off] = r;
        float zl = g_acum[((size_t)(b * Nc + c) * Hh + h) * Ck + (Ck - 1)];
        r = g_states[off] + expf(zl) * r;
    }
}

// ---------------------------------------------------------------------------
// Y_off + combine
// ---------------------------------------------------------------------------
__global__ __launch_bounds__(256) void yoff_kernel(const float* __restrict__ Dv) {
    int bc = blockIdx.x, h = blockIdx.y, lT = blockIdx.z;
    int b = bc / Nc, c = bc % Nc;
    int tid = threadIdx.x;
    int ty = tid >> 4, tx = tid & 15;
    __shared__ float Cs[16][65];
    __shared__ float Ps[16][65];
    __shared__ float lAc[64];
    const float* acumC = g_acum + ((size_t)bc * Hh + h) * Ck;
    if (tid < 64) lAc[tid] = acumC[lT * 64 + tid];
    int rowbase = b * Ll + c * Ck + lT * 64;
    const float* pprev = g_prev + ((size_t)bc * Hh + h) * Pp * Nn;

    float acc[4][4];
#pragma unroll
    for (int i = 0; i < 4; i++)
#pragma unroll
        for (int j = 0; j < 4; j++) acc[i][j] = 0.f;

    int lrow = tid >> 2;
    int lcol = (tid & 3) * 4;
    for (int n0 = 0; n0 < Nn; n0 += 16) {
        const float* pc = g_conv + (size_t)(rowbase + lrow) * ConvD + Inter + Nn + n0 + lcol;
#pragma unroll
        for (int u = 0; u < 4; u++) Cs[lcol + u][lrow] = pc[u];
        const float* pp = pprev + (size_t)lrow * Nn + n0 + lcol;
#pragma unroll
        for (int u = 0; u < 4; u++) Ps[lcol + u][lrow] = pp[u];
        __syncthreads();
#pragma unroll
        for (int kk = 0; kk < 16; kk++) {
            float rc[4], rp[4];
#pragma unroll
            for (int i = 0; i < 4; i++) rc[i] = Cs[kk][ty * 4 + i];
#pragma unroll
            for (int j = 0; j < 4; j++) rp[j] = Ps[kk][tx * 4 + j];
#pragma unroll
            for (int i = 0; i < 4; i++)
#pragma unroll
                for (int j = 0; j < 4; j++) acc[i][j] += rc[i] * rp[j];
        }
        __syncthreads();
    }
    float Dh = Dv[h];
#pragma unroll
    for (int i = 0; i < 4; i++) {
        int ll = ty * 4 + i;
        int l = rowbase + ll;
        float sd = expf(lAc[ll]);
        const float* ph = g_conv + (size_t)l * ConvD + h * Pp;
        float* py = g_y + (size_t)l * Inter + h * Pp;
#pragma unroll
        for (int j = 0; j < 4; j++) {
            int p = tx * 4 + j;
            py[p] = py[p] + acc[i][j] * sd + Dh * ph[p];
        }
    }
}

// ---------------------------------------------------------------------------
// Gated RMSNorm; writes fp16-rounded y for the 1-pass out-proj
// ---------------------------------------------------------------------------
__global__ __launch_bounds__(256) void norm_kernel(const float* __restrict__ norm_w) {
    int row = blockIdx.x;
    int tid = threadIdx.x;
    const float* pg = g_proj + (size_t)row * ProjD;
    const float* py = g_y + (size_t)row * Inter;
    float f[8];
    float ss = 0.f;
#pragma unroll
    for (int u = 0; u < 8; u++) {
        int i = tid + u * 256;
        float g = pg[i];
        float v = py[i] * siluf(g);
        f[u] = v;
        ss += v * v;
    }
    __shared__ float red[8];
    int lane = tid & 31, wid = tid >> 5;
#pragma unroll
    for (int o = 16; o > 0; o >>= 1) ss += __shfl_xor_sync(0xffffffffu, ss, o);
    if (lane == 0) red[wid] = ss;
    __syncthreads();
    if (tid == 0) {
        float t = 0.f;
#pragma unroll
        for (int i = 0; i < 8; i++) t += red[i];
        red[0] = t;
    }
    __syncthreads();
    float rs = rsqrtf(red[0] / (float)Inter + 1e-6f);
#pragma unroll
    for (int u = 0; u < 8; u++) {
        int i = tid + u * 256;
        float v = f[u] * rs * norm_w[i];
        g_Ah[(size_t)row * Inter + i] = __float2half(v);
    }
}

// ---------------------------------------------------------------------------
// Launch
// ---------------------------------------------------------------------------
extern "C" void kernel_launch(void* const* d_in, const int* in_sizes, int n_in,
                              void* d_out, int out_size) {
    const float* x         = (const float*)d_in[0];
    const float* in_proj_w = (const float*)d_in[1];
    const float* conv_w    = (const float*)d_in[2];
    const float* conv_b    = (const float*)d_in[3];
    const float* dt_bias   = (const float*)d_in[4];
    const float* A_log     = (const float*)d_in[5];
    const float* Dv        = (const float*)d_in[6];
    const float* norm_w    = (const float*)d_in[7];
    const float* out_proj_w= (const float*)d_in[8];
    float* out = (float*)d_out;

    cudaFuncSetAttribute(gemm_in_kernel, cudaFuncAttributeMaxDynamicSharedMemorySize, GEMM_SMEM);
    cudaFuncSetAttribute(gemm_out_kernel, cudaFuncAttributeMaxDynamicSharedMemorySize, GEMM_SMEM);

    // 1) round x and in_proj_w to fp16
    {
        int n = BL * Dm;
        round_x_kernel<<<(n + 255) / 256, 256>>>(x, n);
        n = ProjD * Dm;
        round_w_kernel<<<(n + 255) / 256, 256>>>(in_proj_w, n);
    }
    // 2) in-projection GEMM (1-pass fp16)
    {
        dim3 grid((ProjD + 127) / 128, BL / 128);
        gemm_in_kernel<<<grid, 256, GEMM_SMEM>>>();
    }
    // 3) conv + SiLU (higher occupancy)
    {
        dim3 grid(ConvD / 256, Ll / 32, Bb);
        conv_silu_kernel<<<grid, 256>>>(conv_w, conv_b);
    }
    // 4) cumsum of dt*A (fused softplus)
    acum_kernel<<<Bb * Nc * Hh, Ck>>>(A_log, dt_bias);
    // 5) Gm = C B^T
    {
        dim3 grid(Bb * Nc, Ck / 64, Ck / 64);
        gm_kernel<<<grid, 256>>>();
    }
    // 6) Y_diag
    {
        dim3 grid(Bb * Nc, Hh, Ck / 64);
        ydiag_kernel<<<grid, 256>>>();
    }
    // 7) states
    {
        dim3 grid(Bb * Nc, Hh);
        states_kernel<<<grid, 256>>>();
    }
    // 8) inter-chunk recurrence
    {
        int total = Bb * Hh * Pp * Nn;
        prev_kernel<<<(total + 255) / 256, 256>>>();
    }
    // 9) Y_off + combine
    {
        dim3 grid(Bb * Nc, Hh, Ck / 64);
        yoff_kernel<<<grid, 256>>>(Dv);
    }
    // 10) gated RMSNorm (writes fp16 y)
    norm_kernel<<<BL, 256>>>(norm_w);
    // 11) round out_proj_w to fp16
    {
        int n = Dm * Inter;
        round_w_kernel<<<(n + 255) / 256, 256>>>(out_proj_w, n);
    }
    // 12) out-projection GEMM (1-pass fp16)
    {
        dim3 grid(Dm / 128, BL / 128);
        gemm_out_kernel<<<grid, 256, GEMM_SMEM>>>(out);
    }
    (void)in_sizes; (void)n_in; (void)out_size;
}

// round 11
// speedup vs baseline: 2.1028x; 1.3946x over previous
#include <cuda_runtime.h>
#include <cuda_fp16.h>
#include <math.h>
#include <stdint.h>

// ---------------------------------------------------------------------------
// Problem constants (fixed shapes)
// ---------------------------------------------------------------------------
#define Bb     2
#define Ll     2048
#define Dm     1024
#define Hh     32
#define Pp     64
#define Nn     128
#define KCONV  4
#define Ck     256
#define Nc     8          // Ll / Ck
#define Inter  2048
#define ConvD  2304
#define ProjD  4384
#define BL     (Bb * Ll)  // 4096

// ---------------------------------------------------------------------------
// Scratch (device globals; no dynamic allocation allowed)
// ---------------------------------------------------------------------------
__device__ float g_proj[(size_t)BL * ProjD];
__device__ float g_conv[(size_t)BL * ConvD];
__device__ float g_dtv[(size_t)BL * Hh];
__device__ float g_acum[(size_t)Bb * Nc * Hh * Ck];
__device__ float g_gm[(size_t)Bb * Nc * Ck * Ck];
__device__ float g_y[(size_t)BL * Inter];
__device__ float g_states[(size_t)Bb * Nc * Hh * Pp * Nn];
__device__ float g_prev[(size_t)Bb * Nc * Hh * Pp * Nn];

// fp16 buffers
__device__ __half g_Ah[(size_t)BL * Inter];
__device__ __half g_Bh[(size_t)ProjD * Dm];

__device__ __forceinline__ float siluf(float x) { return x / (1.f + expf(-x)); }

__device__ __forceinline__ float4 ldg4(const float* p) {
    return *reinterpret_cast<const float4*>(p);
}

// ---------------------------------------------------------------------------
// PTX helpers
// ---------------------------------------------------------------------------
__device__ __forceinline__ unsigned su32(const void* p) {
    return (unsigned)__cvta_generic_to_shared(p);
}

__device__ __forceinline__ void cp16(unsigned dst, const void* src, bool ok) {
    int sz = ok ? 16 : 0;
    asm volatile("cp.async.cg.shared.global [%0], [%1], 16, %2;\n"
                 :: "r"(dst), "l"(src), "r"(sz));
}

__device__ __forceinline__ void ldsm4(unsigned& r0, unsigned& r1, unsigned& r2, unsigned& r3,
                                      unsigned addr) {
    asm volatile("ldmatrix.sync.aligned.m8n8.x4.shared.b16 {%0,%1,%2,%3}, [%4];"
                 : "=r"(r0), "=r"(r1), "=r"(r2), "=r"(r3) : "r"(addr));
}

__device__ __forceinline__ void mma16816(float* c, const unsigned* a, const unsigned* b) {
    asm volatile(
        "mma.sync.aligned.m16n8k16.row.col.f32.f16.f16.f32 "
        "{%0,%1,%2,%3}, {%4,%5,%6,%7}, {%8,%9}, {%0,%1,%2,%3};"
        : "+f"(c[0]), "+f"(c[1]), "+f"(c[2]), "+f"(c[3])
        : "r"(a[0]), "r"(a[1]), "r"(a[2]), "r"(a[3]), "r"(b[0]), "r"(b[1]));
}

// ---------------------------------------------------------------------------
// Tensor-core fp16 GEMM, 1-pass: C = Ah*Bh, fp32 accum. (unchanged from R10)
// ---------------------------------------------------------------------------
#define GEMM_SMEM (2 * 36864)

struct Frags {
    unsigned ah[4][4];
    unsigned bh[4][2];
};

__device__ __forceinline__ void load_frags(Frags& F, unsigned stg, int ks,
                                           int wm, int wn, int lane) {
    const int rA = lane & 15;
    const int cB = ((lane >> 4) << 4);
    const unsigned colb = (unsigned)(ks * 32 + cB);
#pragma unroll
    for (int mf = 0; mf < 4; mf++) {
        unsigned ra = stg + (wm * 64 + mf * 16 + rA) * 144 + colb;
        ldsm4(F.ah[mf][0], F.ah[mf][1], F.ah[mf][2], F.ah[mf][3], ra);
    }
#pragma unroll
    for (int nf2 = 0; nf2 < 2; nf2++) {
        unsigned rb = stg + 18432 + (wn * 32 + nf2 * 16 + rA) * 144 + colb;
        unsigned t0, t1, t2, t3;
        ldsm4(t0, t1, t2, t3, rb);
        F.bh[nf2 * 2][0] = t0; F.bh[nf2 * 2][1] = t2;
        F.bh[nf2 * 2 + 1][0] = t1; F.bh[nf2 * 2 + 1][1] = t3;
    }
}

__device__ __forceinline__ void gemm_core(const __half* __restrict__ Ah,
                                          const __half* __restrict__ Bh,
                                          float* __restrict__ C,
                                          int M, int N, int K) {
    extern __shared__ char dyn[];
    const unsigned sbase = su32(dyn);
    const int tid = threadIdx.x;
    const int lane = tid & 31;
    const int warp = tid >> 5;
    const int wm = warp >> 2;
    const int wn = warp & 3;
    const int m0 = blockIdx.y * 128;
    const int n0 = blockIdx.x * 128;
    const int KB = K >> 6;

    float acc[4][4][4];
#pragma unroll
    for (int a = 0; a < 4; a++)
#pragma unroll
        for (int b = 0; b < 4; b++)
#pragma unroll
            for (int c = 0; c < 4; c++) acc[a][b][c] = 0.f;

    auto issue = [&](int kc, int st) {
        unsigned stg = sbase + st * 36864;
#pragma unroll
        for (int i = 0; i < 8; i++) {
            int q = tid + (i << 8);
            int mat = q >> 10;
            int r = (q >> 3) & 127;
            int c16 = q & 7;
            const __half* base = mat ? Bh : Ah;
            int gr = (mat ? n0 : m0) + r;
            bool ok = gr < (mat ? N : M);
            if (!ok) gr = (mat ? N : M) - 1;
            const void* src = base + (size_t)gr * K + (kc << 6) + (c16 << 3);
            unsigned dst = stg + mat * 18432 + r * 144 + (c16 << 4);
            cp16(dst, src, ok);
        }
        asm volatile("cp.async.commit_group;\n");
    };

    issue(0, 0);
    if (KB > 1) issue(1, 1);

    Frags F[2];

    for (int kb = 0; kb < KB; kb++) {
        int st = kb & 1;
        if (kb + 1 < KB) asm volatile("cp.async.wait_group 1;\n");
        else             asm volatile("cp.async.wait_group 0;\n");
        __syncthreads();
        unsigned stg = sbase + st * 36864;

        load_frags(F[0], stg, 0, wm, wn, lane);
#pragma unroll
        for (int ks = 0; ks < 4; ks++) {
            if (ks < 3) load_frags(F[(ks + 1) & 1], stg, ks + 1, wm, wn, lane);
            Frags& f = F[ks & 1];
#pragma unroll
            for (int mf = 0; mf < 4; mf++)
#pragma unroll
                for (int nf = 0; nf < 4; nf++)
                    mma16816(acc[mf][nf], f.ah[mf], f.bh[nf]);
        }
        __syncthreads();
        if (kb + 2 < KB) issue(kb + 2, st);
    }

    int g4 = lane >> 2, t4 = lane & 3;
#pragma unroll
    for (int mf = 0; mf < 4; mf++) {
        int r0 = m0 + wm * 64 + mf * 16 + g4;
#pragma unroll
        for (int nf = 0; nf < 4; nf++) {
            int cg = n0 + wn * 32 + nf * 8 + t4 * 2;
            if (cg < N) {
                float* p0 = C + (size_t)r0 * N + cg;
                p0[0] = acc[mf][nf][0];
                p0[1] = acc[mf][nf][1];
                float* p1 = p0 + (size_t)8 * N;
                p1[0] = acc[mf][nf][2];
                p1[1] = acc[mf][nf][3];
            }
        }
    }
}

__global__ __launch_bounds__(256) void gemm_in_kernel() {
    gemm_core(g_Ah, g_Bh, g_proj, BL, ProjD, Dm);
}

__global__ __launch_bounds__(256) void gemm_out_kernel(float* __restrict__ out) {
    gemm_core(g_Ah, g_Bh, out, BL, Dm, Inter);
}

// ---------------------------------------------------------------------------
// fp16 conversions
// ---------------------------------------------------------------------------
__global__ void round_x_kernel(const float* __restrict__ in, int n) {
    int i = blockIdx.x * blockDim.x + threadIdx.x;
    if (i >= n) return;
    g_Ah[i] = __float2half(in[i]);
}

__global__ void round_w_kernel(const float* __restrict__ in, int n) {
    int i = blockIdx.x * blockDim.x + threadIdx.x;
    if (i >= n) return;
    g_Bh[i] = __float2half(in[i]);
}

// ---------------------------------------------------------------------------
// Depthwise causal conv1d + SiLU (sliding window, 32 positions/thread)
// ---------------------------------------------------------------------------
__global__ __launch_bounds__(256) void conv_silu_kernel(const float* __restrict__ cw,
                                                        const float* __restrict__ cb) {
    int ch = blockIdx.x * 256 + threadIdx.x;
    int l0 = blockIdx.y * 32;
    int b  = blockIdx.z;
    const float* col = g_proj + (size_t)b * Ll * ProjD + Inter + ch;
    float w0 = cw[ch * KCONV + 0];
    float w1 = cw[ch * KCONV + 1];
    float w2 = cw[ch * KCONV + 2];
    float w3 = cw[ch * KCONV + 3];
    float bias = cb[ch];
    float xm3 = (l0 >= 3) ? col[(size_t)(l0 - 3) * ProjD] : 0.f;
    float xm2 = (l0 >= 2) ? col[(size_t)(l0 - 2) * ProjD] : 0.f;
    float xm1 = (l0 >= 1) ? col[(size_t)(l0 - 1) * ProjD] : 0.f;
    float* outp = g_conv + (size_t)(b * Ll + l0) * ConvD + ch;
#pragma unroll 4
    for (int i = 0; i < 32; i++) {
        float x0 = col[(size_t)(l0 + i) * ProjD];
        float acc = bias + w0 * xm3 + w1 * xm2 + w2 * xm1 + w3 * x0;
        outp[(size_t)i * ConvD] = siluf(acc);
        xm3 = xm2; xm2 = xm1; xm1 = x0;
    }
}

// ---------------------------------------------------------------------------
// Per-chunk inclusive cumsum of dt * A with fused softplus
// ---------------------------------------------------------------------------
__global__ void acum_kernel(const float* __restrict__ A_log,
                            const float* __restrict__ dt_bias) {
    int blk = blockIdx.x;
    int h = blk % Hh;
    int bc = blk / Hh;
    int b = bc / Nc, c = bc % Nc;
    int t = threadIdx.x;
    float A = -expf(A_log[h]);
    int bl = b * Ll + c * Ck + t;
    float raw = g_proj[(size_t)bl * ProjD + Inter + ConvD + h] + dt_bias[h];
    float dt = (raw > 20.f) ? raw : log1pf(expf(raw));
    g_dtv[(size_t)bl * Hh + h] = dt;
    float v = dt * A;
    __shared__ float s[Ck];
    s[t] = v;
    __syncthreads();
    for (int off = 1; off < Ck; off <<= 1) {
        float x = (t >= off) ? s[t - off] : 0.f;
        __syncthreads();
        s[t] += x;
        __syncthreads();
    }
    g_acum[(size_t)blk * Ck + t] = s[t];
}

// ---------------------------------------------------------------------------
// Gm[s,z] = sum_n C[s,n] * B[z,n] per (b,c), lower triangle (float4 inner)
// ---------------------------------------------------------------------------
__global__ __launch_bounds__(256) void gm_kernel() {
    int bc = blockIdx.x;
    int sT = blockIdx.y, zT = blockIdx.z;
    if (zT > sT) return;
    int b = bc / Nc, c = bc % Nc;
    int rowbase = b * Ll + c * Ck;
    __shared__ __align__(16) float Cs[16][68];
    __shared__ __align__(16) float Bs[16][68];
    int tid = threadIdx.x;
    int ty = tid >> 4, tx = tid & 15;
    float acc[4][4];
#pragma unroll
    for (int i = 0; i < 4; i++)
#pragma unroll
        for (int j = 0; j < 4; j++) acc[i][j] = 0.f;

    int lrow = tid >> 2;
    int lcol = (tid & 3) * 4;

    for (int n0 = 0; n0 < Nn; n0 += 16) {
        float4 vc = ldg4(g_conv + (size_t)(rowbase + sT * 64 + lrow) * ConvD + Inter + Nn + n0 + lcol);
        float4 vb = ldg4(g_conv + (size_t)(rowbase + zT * 64 + lrow) * ConvD + Inter + n0 + lcol);
        Cs[lcol + 0][lrow] = vc.x; Cs[lcol + 1][lrow] = vc.y;
        Cs[lcol + 2][lrow] = vc.z; Cs[lcol + 3][lrow] = vc.w;
        Bs[lcol + 0][lrow] = vb.x; Bs[lcol + 1][lrow] = vb.y;
        Bs[lcol + 2][lrow] = vb.z; Bs[lcol + 3][lrow] = vb.w;
        __syncthreads();
#pragma unroll
        for (int kk = 0; kk < 16; kk++) {
            float4 rc = *(const float4*)&Cs[kk][ty * 4];
            float4 rb = *(const float4*)&Bs[kk][tx * 4];
            float rcv[4] = {rc.x, rc.y, rc.z, rc.w};
            float rbv[4] = {rb.x, rb.y, rb.z, rb.w};
#pragma unroll
            for (int i = 0; i < 4; i++)
#pragma unroll
                for (int j = 0; j < 4; j++) acc[i][j] += rcv[i] * rbv[j];
        }
        __syncthreads();
    }
#pragma unroll
    for (int i = 0; i < 4; i++) {
        int sg = sT * 64 + ty * 4 + i;
        float* pg = g_gm + ((size_t)bc * Ck + sg) * Ck + zT * 64 + tx * 4;
        float4 v = make_float4(acc[i][0], acc[i][1], acc[i][2], acc[i][3]);
        *reinterpret_cast<float4*>(pg) = v;
    }
}

// ---------------------------------------------------------------------------
// Y_diag — Ms scalar (pad 65, conflict-tuned writes); Hs float4 (pad 68)
// ---------------------------------------------------------------------------
__global__ __launch_bounds__(256) void ydiag_kernel() {
    int bc = blockIdx.x;
    int h = blockIdx.y;
    int sT = blockIdx.z;
    int b = bc / Nc, c = bc % Nc;
    int tid = threadIdx.x;
    int ty = tid >> 4, tx = tid & 15;

    __shared__ float Ms[64][65];
    __shared__ __align__(16) float Hs[64][68];
    __shared__ float sAc[64], zAc[64], ezs[64];

    const float* acumC = g_acum + ((size_t)bc * Hh + h) * Ck;
    if (tid < 64) sAc[tid] = acumC[sT * 64 + tid];
    int rowbase = b * Ll + c * Ck;

    float acc[4][4];
#pragma unroll
    for (int i = 0; i < 4; i++)
#pragma unroll
        for (int j = 0; j < 4; j++) acc[i][j] = 0.f;

    for (int zT = 0; zT <= sT; zT++) {
        float M = acumC[zT * 64 + 63];
        if (tid < 64) {
            float az = acumC[zT * 64 + tid];
            zAc[tid] = az;
            ezs[tid] = expf(M - az);
        }
        {
            int zz = tid >> 2;
            int p0 = (tid & 3) * 16;
            int l = rowbase + zT * 64 + zz;
            float d = g_dtv[(size_t)l * Hh + h];
            const float* ph = g_conv + (size_t)l * ConvD + h * Pp + p0;
#pragma unroll
            for (int u = 0; u < 4; u++) {
                float4 v = ldg4(ph + u * 4);
                float4 w = make_float4(v.x * d, v.y * d, v.z * d, v.w * d);
                *reinterpret_cast<float4*>(&Hs[zz][p0 + u * 4]) = w;
            }
        }
        __syncthreads();
        {
            int zz4 = (tid & 15) * 4;
            int ss4 = (tid >> 4) * 4;
            if (zT < sT) {
#pragma unroll
                for (int a = 0; a < 4; a++) {
                    int ss = ss4 + a;
                    int sg = sT * 64 + ss;
                    float es = expf(sAc[ss] - M);
                    float4 g = ldg4(g_gm + ((size_t)bc * Ck + sg) * Ck + zT * 64 + zz4);
                    Ms[zz4 + 0][ss] = g.x * ezs[zz4 + 0] * es;
                    Ms[zz4 + 1][ss] = g.y * ezs[zz4 + 1] * es;
                    Ms[zz4 + 2][ss] = g.z * ezs[zz4 + 2] * es;
                    Ms[zz4 + 3][ss] = g.w * ezs[zz4 + 3] * es;
                }
            } else {
#pragma unroll
                for (int a = 0; a < 4; a++) {
                    int ss = ss4 + a;
                    int sg = sT * 64 + ss;
                    float as = sAc[ss];
                    float4 g = ldg4(g_gm + ((size_t)bc * Ck + sg) * Ck + zT * 64 + zz4);
                    float gv[4] = {g.x, g.y, g.z, g.w};
#pragma unroll
                    for (int q = 0; q < 4; q++) {
                        int zz = zz4 + q;
                        float m = 0.f;
                        if ((zT * 64 + zz) <= sg)
                            m = gv[q] * expf(as - zAc[zz]);
                        Ms[zz][ss] = m;
                    }
                }
            }
        }
        __syncthreads();
#pragma unroll 4
        for (int zz = 0; zz < 64; zz++) {
            float rm[4];
#pragma unroll
            for (int i = 0; i < 4; i++) rm[i] = Ms[zz][ty * 4 + i];
            float4 rh = *(const float4*)&Hs[zz][tx * 4];
            float rhv[4] = {rh.x, rh.y, rh.z, rh.w};
#pragma unroll
            for (int i = 0; i < 4; i++)
#pragma unroll
                for (int j = 0; j < 4; j++) acc[i][j] += rm[i] * rhv[j];
        }
        __syncthreads();
    }
#pragma unroll
    for (int i = 0; i < 4; i++) {
        int l = rowbase + sT * 64 + ty * 4 + i;
        float* py = g_y + (size_t)l * Inter + h * Pp + tx * 4;
        *reinterpret_cast<float4*>(py) = make_float4(acc[i][0], acc[i][1], acc[i][2], acc[i][3]);
    }
}

// ---------------------------------------------------------------------------
// states — float4 inner loads
// ---------------------------------------------------------------------------
__global__ __launch_bounds__(256) void states_kernel() {
    int bc = blockIdx.x, h = blockIdx.y;
    int b = bc / Nc, c = bc % Nc;
    int tid = threadIdx.x;
    int ty = tid >> 4, tx = tid & 15;
    __shared__ __align__(16) float Hd[32][68];
    __shared__ __align__(16) float Bsm[32][132];
    const float* acumC = g_acum + ((size_t)bc * Hh + h) * Ck;
    float aLast = acumC[Ck - 1];
    int rowbase = b * Ll + c * Ck;
    float acc[4][8];
#pragma unroll
    for (int i = 0; i < 4; i++)
#pragma unroll
        for (int j = 0; j < 8; j++) acc[i][j] = 0.f;

    for (int l0 = 0; l0 < Ck; l0 += 32) {
        {
            int ll = tid >> 3;
            int p0 = (tid & 7) * 8;
            int l = rowbase + l0 + ll;
            float w = g_dtv[(size_t)l * Hh + h] * expf(aLast - acumC[l0 + ll]);
            const float* ph = g_conv + (size_t)l * ConvD + h * Pp + p0;
#pragma unroll
            for (int u = 0; u < 2; u++) {
                float4 v = ldg4(ph + u * 4);
                *reinterpret_cast<float4*>(&Hd[ll][p0 + u * 4]) =
                    make_float4(v.x * w, v.y * w, v.z * w, v.w * w);
            }
        }
        {
            int ll = tid >> 3;
            int n0v = (tid & 7) * 16;
            const float* pb = g_conv + (size_t)(rowbase + l0 + ll) * ConvD + Inter + n0v;
#pragma unroll
            for (int u = 0; u < 4; u++)
                *reinterpret_cast<float4*>(&Bsm[ll][n0v + u * 4]) = ldg4(pb + u * 4);
        }
        __syncthreads();
#pragma unroll 4
        for (int ll = 0; ll < 32; ll++) {
            float4 rh4 = *(const float4*)&Hd[ll][ty * 4];
            float4 rb0 = *(const float4*)&Bsm[ll][tx * 8];
            float4 rb1 = *(const float4*)&Bsm[ll][tx * 8 + 4];
            float rh[4] = {rh4.x, rh4.y, rh4.z, rh4.w};
            float rb[8] = {rb0.x, rb0.y, rb0.z, rb0.w, rb1.x, rb1.y, rb1.z, rb1.w};
#pragma unroll
            for (int i = 0; i < 4; i++)
#pragma unroll
                for (int j = 0; j < 8; j++) acc[i][j] += rh[i] * rb[j];
        }
        __syncthreads();
    }
    float* ps = g_states + ((size_t)bc * Hh + h) * Pp * Nn;
#pragma unroll
    for (int i = 0; i < 4; i++) {
        float* p = ps + (ty * 4 + i) * Nn + tx * 8;
        *reinterpret_cast<float4*>(p) = make_float4(acc[i][0], acc[i][1], acc[i][2], acc[i][3]);
        *reinterpret_cast<float4*>(p + 4) = make_float4(acc[i][4], acc[i][5], acc[i][6], acc[i][7]);
    }
}

// ---------------------------------------------------------------------------
// Inter-chunk recurrence
// ---------------------------------------------------------------------------
__global__ void prev_kernel() {
    int idx = blockIdx.x * blockDim.x + threadIdx.x;
    if (idx >= Bb * Hh * Pp * Nn) return;
    int n = idx % Nn;
    int p = (idx / Nn) % Pp;
    int h = (idx / (Nn * Pp)) % Hh;
    int b = idx / (Nn * Pp * Hh);
    float r = 0.f;
    for (int c = 0; c < Nc; c++) {
        size_t off = (((size_t)(b * Nc + c) * Hh + h) * Pp + p) * Nn + n;
        g_prev[off] = r;
        float zl = g_acum[((size_t)(b * Nc + c) * Hh + h) * Ck + (Ck - 1)];
        r = g_states[off] + expf(zl) * r;
    }
}

// ---------------------------------------------------------------------------
// Y_off + combine — float4 inner loads + vector epilogue
// ---------------------------------------------------------------------------
__global__ __launch_bounds__(256) void yoff_kernel(const float* __restrict__ Dv) {
    int bc = blockIdx.x, h = blockIdx.y, lT = blockIdx.z;
    int b = bc / Nc, c = bc % Nc;
    int tid = threadIdx.x;
    int ty = tid >> 4, tx = tid & 15;
    __shared__ __align__(16) float Cs[16][68];
    __shared__ __align__(16) float Ps[16][68];
    __shared__ float lAc[64];
    const float* acumC = g_acum + ((size_t)bc * Hh + h) * Ck;
    if (tid < 64) lAc[tid] = acumC[lT * 64 + tid];
    int rowbase = b * Ll + c * Ck + lT * 64;
    const float* pprev = g_prev + ((size_t)bc * Hh + h) * Pp * Nn;

    float acc[4][4];
#pragma unroll
    for (int i = 0; i < 4; i++)
#pragma unroll
        for (int j = 0; j < 4; j++) acc[i][j] = 0.f;

    int lrow = tid >> 2;
    int lcol = (tid & 3) * 4;
    for (int n0 = 0; n0 < Nn; n0 += 16) {
        float4 vc = ldg4(g_conv + (size_t)(rowbase + lrow) * ConvD + Inter + Nn + n0 + lcol);
        Cs[lcol + 0][lrow] = vc.x; Cs[lcol + 1][lrow] = vc.y;
        Cs[lcol + 2][lrow] = vc.z; Cs[lcol + 3][lrow] = vc.w;
        float4 vp = ldg4(pprev + (size_t)lrow * Nn + n0 + lcol);
        Ps[lcol + 0][lrow] = vp.x; Ps[lcol + 1][lrow] = vp.y;
        Ps[lcol + 2][lrow] = vp.z; Ps[lcol + 3][lrow] = vp.w;
        __syncthreads();
#pragma unroll
        for (int kk = 0; kk < 16; kk++) {
            float4 rc = *(const float4*)&Cs[kk][ty * 4];
            float4 rp = *(const float4*)&Ps[kk][tx * 4];
            float rcv[4] = {rc.x, rc.y, rc.z, rc.w};
            float rpv[4] = {rp.x, rp.y, rp.z, rp.w};
#pragma unroll
            for (int i = 0; i < 4; i++)
#pragma unroll
                for (int j = 0; j < 4; j++) acc[i][j] += rcv[i] * rpv[j];
        }
        __syncthreads();
    }
    float Dh = Dv[h];
#pragma unroll
    for (int i = 0; i < 4; i++) {
        int ll = ty * 4 + i;
        int l = rowbase + ll;
        float sd = expf(lAc[ll]);
        float4 hv = ldg4(g_conv + (size_t)l * ConvD + h * Pp + tx * 4);
        float* py = g_y + (size_t)l * Inter + h * Pp + tx * 4;
        float4 yv = *reinterpret_cast<float4*>(py);
        yv.x = yv.x + acc[i][0] * sd + Dh * hv.x;
        yv.y = yv.y + acc[i][1] * sd + Dh * hv.y;
        yv.z = yv.z + acc[i][2] * sd + Dh * hv.z;
        yv.w = yv.w + acc[i][3] * sd + Dh * hv.w;
        *reinterpret_cast<float4*>(py) = yv;
    }
}

// ---------------------------------------------------------------------------
// Gated RMSNorm; writes fp16-rounded y for the 1-pass out-proj
// ---------------------------------------------------------------------------
__global__ __launch_bounds__(256) void norm_kernel(const float* __restrict__ norm_w) {
    int row = blockIdx.x;
    int tid = threadIdx.x;
    const float* pg = g_proj + (size_t)row * ProjD;
    const float* py = g_y + (size_t)row * Inter;
    float f[8];
    float ss = 0.f;
#pragma unroll
    for (int u = 0; u < 8; u++) {
        int i = tid + u * 256;
        float g = pg[i];
        float v = py[i] * siluf(g);
        f[u] = v;
        ss += v * v;
    }
    __shared__ float red[8];
    int lane = tid & 31, wid = tid >> 5;
#pragma unroll
    for (int o = 16; o > 0; o >>= 1) ss += __shfl_xor_sync(0xffffffffu, ss, o);
    if (lane == 0) red[wid] = ss;
    __syncthreads();
    if (tid == 0) {
        float t = 0.f;
#pragma unroll
        for (int i = 0; i < 8; i++) t += red[i];
        red[0] = t;
    }
    __syncthreads();
    float rs = rsqrtf(red[0] / (float)Inter + 1e-6f);
#pragma unroll
    for (int u = 0; u < 8; u++) {
        int i = tid + u * 256;
        float v = f[u] * rs * norm_w[i];
        g_Ah[(size_t)row * Inter + i] = __float2half(v);
    }
}

// ---------------------------------------------------------------------------
// Launch
// ---------------------------------------------------------------------------
extern "C" void kernel_launch(void* const* d_in, const int* in_sizes, int n_in,
                              void* d_out, int out_size) {
    const float* x         = (const float*)d_in[0];
    const float* in_proj_w = (const float*)d_in[1];
    const float* conv_w    = (const float*)d_in[2];
    const float* conv_b    = (const float*)d_in[3];
    const float* dt_bias   = (const float*)d_in[4];
    const float* A_log     = (const float*)d_in[5];
    const float* Dv        = (const float*)d_in[6];
    const float* norm_w    = (const float*)d_in[7];
    const float* out_proj_w= (const float*)d_in[8];
    float* out = (float*)d_out;

    cudaFuncSetAttribute(gemm_in_kernel, cudaFuncAttributeMaxDynamicSharedMemorySize, GEMM_SMEM);
    cudaFuncSetAttribute(gemm_out_kernel, cudaFuncAttributeMaxDynamicSharedMemorySize, GEMM_SMEM);

    // 1) round x and in_proj_w to fp16
    {
        int n = BL * Dm;
        round_x_kernel<<<(n + 255) / 256, 256>>>(x, n);
        n = ProjD * Dm;
        round_w_kernel<<<(n + 255) / 256, 256>>>(in_proj_w, n);
    }
    // 2) in-projection GEMM (1-pass fp16)
    {
        dim3 grid((ProjD + 127) / 128, BL / 128);
        gemm_in_kernel<<<grid, 256, GEMM_SMEM>>>();
    }
    // 3) conv + SiLU
    {
        dim3 grid(ConvD / 256, Ll / 32, Bb);
        conv_silu_kernel<<<grid, 256>>>(conv_w, conv_b);
    }
    // 4) cumsum of dt*A (fused softplus)
    acum_kernel<<<Bb * Nc * Hh, Ck>>>(A_log, dt_bias);
    // 5) Gm = C B^T
    {
        dim3 grid(Bb * Nc, Ck / 64, Ck / 64);
        gm_kernel<<<grid, 256>>>();
    }
    // 6) Y_diag
    {
        dim3 grid(Bb * Nc, Hh, Ck / 64);
        ydiag_kernel<<<grid, 256>>>();
    }
    // 7) states
    {
        dim3 grid(Bb * Nc, Hh);
        states_kernel<<<grid, 256>>>();
    }
    // 8) inter-chunk recurrence
    {
        int total = Bb * Hh * Pp * Nn;
        prev_kernel<<<(total + 255) / 256, 256>>>();
    }
    // 9) Y_off + combine
    {
        dim3 grid(Bb * Nc, Hh, Ck / 64);
        yoff_kernel<<<grid, 256>>>(Dv);
    }
    // 10) gated RMSNorm (writes fp16 y)
    norm_kernel<<<BL, 256>>>(norm_w);
    // 11) round out_proj_w to fp16
    {
        int n = Dm * Inter;
        round_w_kernel<<<(n + 255) / 256, 256>>>(out_proj_w, n);
    }
    // 12) out-projection GEMM (1-pass fp16)
    {
        dim3 grid(Dm / 128, BL / 128);
        gemm_out_kernel<<<grid, 256, GEMM_SMEM>>>(out);
    }
    (void)in_sizes; (void)n_in; (void)out_size;
}